// round 4
// baseline (speedup 1.0000x reference)
#include <cuda_runtime.h>

// RNN_64501818851829 — persistent fp32x2 RNN, GB300 sm_103a. Round 4.
// 128 blocks x 256 threads (8 warps, 2 per SMSP). Block owns 32 rows
// (16 f32x2 row-pairs) for all T=1024 steps.
// Phase A (L1, 80 neurons x k=41): 2-way k-split.
//   thread(tlow, kh): s1=tlow&7 (pairs s1,s1+8), jg1=tlow>>3 (5 neurons),
//   kh=0 -> k 0..19 + bias; kh=1 -> k 20..39 + u-term. Partials via shared.
// Phase B (L2, 40 neurons x k=40): 2-way k-split.
//   s2=tlow&15 (1 pair), jg2=tlow>>4 (5 neurons), kh k-half. 4 barriers/step.

typedef unsigned long long u64;

static constexpr int Bn = 4096;
static constexpr int Tn = 1024;
static constexpr int NTHR = 256;
static constexpr int NBLK = 128;

// shared layout (u64 units)
static constexpr int OFF_WCP  = 0;                  // [20kp][16jg][10]   3200
static constexpr int OFF_WU   = OFF_WCP + 3200;     // [16jg][6]            96
static constexpr int OFF_W2P  = OFF_WU  + 96;       // [20kp][8jg][10]    1600
static constexpr int OFF_COMB = OFF_W2P + 1600;     // [2][16pair][42]    1344
static constexpr int OFF_A    = OFF_COMB + 1344;    // [16pair][42]        672
static constexpr int OFF_PA   = OFF_A   + 672;      // [16jg][8s][10]+pad 1312
static constexpr int OFF_PB   = OFF_PA  + 1312;     // [8jg][16s][6]       768
static constexpr int OFF_OUTP = OFF_PB  + 768;      // [16pair][8]         128
static constexpr int SMEM_U64 = OFF_OUTP + 128;     // 9120 u64
static constexpr int SMEM_BYTES = SMEM_U64 * 8;     // 72960 B

__device__ __forceinline__ u64 fma2(u64 a, u64 b, u64 c) {
    u64 d; asm("fma.rn.f32x2 %0, %1, %2, %3;" : "=l"(d) : "l"(a), "l"(b), "l"(c));
    return d;
}
__device__ __forceinline__ u64 add2(u64 a, u64 b) {
    u64 d; asm("add.rn.f32x2 %0, %1, %2;" : "=l"(d) : "l"(a), "l"(b));
    return d;
}
__device__ __forceinline__ u64 mul2(u64 a, u64 b) {
    u64 d; asm("mul.rn.f32x2 %0, %1, %2;" : "=l"(d) : "l"(a), "l"(b));
    return d;
}
__device__ __forceinline__ u64 pack2(float lo, float hi) {
    u64 d; asm("mov.b64 %0, {%1, %2};" : "=l"(d) : "f"(lo), "f"(hi));
    return d;
}
__device__ __forceinline__ u64 dup2(float x) {
    u64 d; asm("mov.b64 %0, {%1, %1};" : "=l"(d) : "f"(x));
    return d;
}
// exact leaky-relu(0.01): max(x, 0.01*x)
__device__ __forceinline__ u64 lrelu2(u64 x, u64 c001) {
    u64 m = mul2(x, c001);
    float2 xf = *(float2*)&x, mf = *(float2*)&m, r;
    r.x = fmaxf(xf.x, mf.x);
    r.y = fmaxf(xf.y, mf.y);
    return *(u64*)&r;
}

__global__ void __launch_bounds__(NTHR, 1) rnn_kernel(
    const float* __restrict__ inputs,
    const float* __restrict__ w1,  const float* __restrict__ b1,
    const float* __restrict__ w2,  const float* __restrict__ b2,
    const float* __restrict__ ow1, const float* __restrict__ ob1,
    const float* __restrict__ ow2, const float* __restrict__ ob2,
    float* __restrict__ outp)
{
    extern __shared__ __align__(16) u64 sm[];
    u64* sWcP  = sm + OFF_WCP;
    u64* sWu   = sm + OFF_WU;
    u64* sW2P  = sm + OFF_W2P;
    u64* sComb = sm + OFF_COMB;  // [buf][pair][42]: k 0..39 hidden, 40 = u
    u64* sA    = sm + OFF_A;     // [pair][42] h2h activations
    u64* sPA   = sm + OFF_PA;    // A partials: jg*82 + s1*10
    u64* sPB   = sm + OFF_PB;    // B partials: jg2*96 + s2*6
    u64* sOutP = sm + OFF_OUTP;  // [pair][8] h2o partial dots

    const int tid  = threadIdx.x;
    const int tlow = tid & 127;
    const int kh   = tid >> 7;          // k-half: 0 or 1
    const int baseRow = blockIdx.x * 32;

    // ---- weight staging (dup to f32x2, k-paired) ----
    for (int idx = tid; idx < 40 * 80; idx += NTHR) {
        int kk = idx / 80, j = idx % 80;  // logical k (combined col k+1), neuron j
        float w = (j < 40) ? w1[j * 41 + kk + 1] : ow1[(j - 40) * 41 + kk + 1];
        sWcP[(kk >> 1) * 160 + (j / 5) * 10 + (j % 5) * 2 + (kk & 1)] = dup2(w);
    }
    for (int j = tid; j < 80; j += NTHR) {
        float w = (j < 40) ? w1[j * 41] : ow1[(j - 40) * 41];
        sWu[(j / 5) * 6 + (j % 5)] = dup2(w);
    }
    for (int idx = tid; idx < 40 * 40; idx += NTHR) {
        int k = idx / 40, j = idx % 40;
        sW2P[(k >> 1) * 80 + (j / 5) * 10 + (j % 5) * 2 + (k & 1)] = dup2(w2[j * 40 + k]);
    }
    for (int idx = tid; idx < 2 * 16 * 42; idx += NTHR) sComb[idx] = 0ull;

    // ---- roles & constants ----
    const int s1  = tlow & 7,  jg1 = tlow >> 3;   // Phase A
    const int s2  = tlow & 15, jg2 = tlow >> 4;   // Phase B
    const bool isH2H = (jg1 < 8);
    const u64 c001 = dup2(0.01f);

    u64 bA[5], rW[5], bB[5];
    if (kh == 0) {
#pragma unroll
        for (int i = 0; i < 5; i++) {
            int nA = (isH2H ? 5 * jg1 : 5 * (jg1 - 8)) + i;
            bA[i] = isH2H ? dup2(b1[nA]) : dup2(ob1[nA]);
            rW[i] = isH2H ? 0ull : dup2(ow2[5 * (jg1 - 8) + i]);
            bB[i] = dup2(b2[5 * jg2 + i]);
        }
    } else {
#pragma unroll
        for (int i = 0; i < 5; i++) { bA[i] = 0ull; rW[i] = 0ull; bB[i] = 0ull; }
    }
    const u64 bo = dup2(ob2[0]);
    const int r0 = baseRow + 2 * (tlow & 15);  // rows for tlow<16 duties
    const int r1 = r0 + 1;

    __syncthreads();
    if (tid < 16)
        sComb[tid * 42 + 40] = pack2(inputs[(size_t)r0 * Tn], inputs[(size_t)r1 * Tn]);

    const int kpA0 = kh * 10;                  // Phase A kp range [kpA0, kpA0+10)
    const u64* wpA = sWcP + jg1 * 10;
    const u64* wuA = sWu + jg1 * 6;
    const u64* wpB = sW2P + jg2 * 10;
    u64* pA = sPA + jg1 * 82 + s1 * 10;
    u64* pB = sPB + jg2 * 96 + s2 * 6;

    int cur = 0;
    for (int t = 0; t < Tn; t++) {
        __syncthreads();  // b1: comb[cur] ready

        u64 uN = 0ull;
        if (kh == 0 && tlow < 16 && t + 1 < Tn)  // prefetch next input, used at B-finish
            uN = pack2(inputs[(size_t)r0 * Tn + t + 1], inputs[(size_t)r1 * Tn + t + 1]);

        const u64* cbA = sComb + cur * 672 + s1 * 42;
        const u64* cbB = cbA + 8 * 42;

        // ---- Phase A (k-half kh): 5 neurons x 2 pairs ----
        u64 aA0 = bA[0], aA1 = bA[1], aA2 = bA[2], aA3 = bA[3], aA4 = bA[4];
        u64 aB0 = bA[0], aB1 = bA[1], aB2 = bA[2], aB3 = bA[3], aB4 = bA[4];
#pragma unroll
        for (int q = 0; q < 10; q++) {
            int kp = kpA0 + q;
            ulonglong2 ca = *(const ulonglong2*)(cbA + 2 * kp);
            ulonglong2 cb = *(const ulonglong2*)(cbB + 2 * kp);
            const ulonglong2* w = (const ulonglong2*)(wpA + kp * 160);
            ulonglong2 w0 = w[0], w1v = w[1], w2v = w[2], w3v = w[3], w4v = w[4];
            aA0 = fma2(ca.y, w0.y,  fma2(ca.x, w0.x,  aA0));
            aB0 = fma2(cb.y, w0.y,  fma2(cb.x, w0.x,  aB0));
            aA1 = fma2(ca.y, w1v.y, fma2(ca.x, w1v.x, aA1));
            aB1 = fma2(cb.y, w1v.y, fma2(cb.x, w1v.x, aB1));
            aA2 = fma2(ca.y, w2v.y, fma2(ca.x, w2v.x, aA2));
            aB2 = fma2(cb.y, w2v.y, fma2(cb.x, w2v.x, aB2));
            aA3 = fma2(ca.y, w3v.y, fma2(ca.x, w3v.x, aA3));
            aB3 = fma2(cb.y, w3v.y, fma2(cb.x, w3v.x, aB3));
            aA4 = fma2(ca.y, w4v.y, fma2(ca.x, w4v.x, aA4));
            aB4 = fma2(cb.y, w4v.y, fma2(cb.x, w4v.x, aB4));
        }
        if (kh == 1) {  // u-term + store partials
            u64 ua = cbA[40], ub = cbB[40];
            ulonglong2 u01 = *(const ulonglong2*)(wuA);
            ulonglong2 u23 = *(const ulonglong2*)(wuA + 2);
            u64 u4 = wuA[4];
            aA0 = fma2(ua, u01.x, aA0); aB0 = fma2(ub, u01.x, aB0);
            aA1 = fma2(ua, u01.y, aA1); aB1 = fma2(ub, u01.y, aB1);
            aA2 = fma2(ua, u23.x, aA2); aB2 = fma2(ub, u23.x, aB2);
            aA3 = fma2(ua, u23.y, aA3); aB3 = fma2(ub, u23.y, aB3);
            aA4 = fma2(ua, u4,    aA4); aB4 = fma2(ub, u4,    aB4);
            ulonglong2* d = (ulonglong2*)pA;
            d[0] = make_ulonglong2(aA0, aA1);
            d[1] = make_ulonglong2(aA2, aA3);
            d[2] = make_ulonglong2(aA4, aB0);
            d[3] = make_ulonglong2(aB1, aB2);
            d[4] = make_ulonglong2(aB3, aB4);
        }
        __syncthreads();  // b2: A partials ready

        if (kh == 0) {  // A-finish: combine, lrelu, distribute
            const ulonglong2* q = (const ulonglong2*)pA;
            ulonglong2 q0 = q[0], q1 = q[1], q2 = q[2], q3 = q[3], q4 = q[4];
            aA0 = lrelu2(add2(aA0, q0.x), c001);
            aA1 = lrelu2(add2(aA1, q0.y), c001);
            aA2 = lrelu2(add2(aA2, q1.x), c001);
            aA3 = lrelu2(add2(aA3, q1.y), c001);
            aA4 = lrelu2(add2(aA4, q2.x), c001);
            aB0 = lrelu2(add2(aB0, q2.y), c001);
            aB1 = lrelu2(add2(aB1, q3.x), c001);
            aB2 = lrelu2(add2(aB2, q3.y), c001);
            aB3 = lrelu2(add2(aB3, q4.x), c001);
            aB4 = lrelu2(add2(aB4, q4.y), c001);
            if (isH2H) {
                u64* dA = sA + s1 * 42 + 5 * jg1;
                u64* dB = sA + (s1 + 8) * 42 + 5 * jg1;
                dA[0] = aA0; dA[1] = aA1; dA[2] = aA2; dA[3] = aA3; dA[4] = aA4;
                dB[0] = aB0; dB[1] = aB1; dB[2] = aB2; dB[3] = aB3; dB[4] = aB4;
            } else {
                u64 pa = mul2(aA0, rW[0]);
                pa = fma2(aA1, rW[1], pa); pa = fma2(aA2, rW[2], pa);
                pa = fma2(aA3, rW[3], pa); pa = fma2(aA4, rW[4], pa);
                u64 pb = mul2(aB0, rW[0]);
                pb = fma2(aB1, rW[1], pb); pb = fma2(aB2, rW[2], pb);
                pb = fma2(aB3, rW[3], pb); pb = fma2(aB4, rW[4], pb);
                sOutP[s1 * 8 + (jg1 - 8)] = pa;
                sOutP[(s1 + 8) * 8 + (jg1 - 8)] = pb;
            }
        }
        __syncthreads();  // b3: acts + out partials ready

        // ---- Phase B (k-half kh): 5 neurons x 1 pair ----
        const u64* ap = sA + s2 * 42;
        u64 h0 = bB[0], h1 = bB[1], h2 = bB[2], h3 = bB[3], h4 = bB[4];
#pragma unroll
        for (int q = 0; q < 10; q++) {
            int kp = kpA0 + q;
            ulonglong2 av = *(const ulonglong2*)(ap + 2 * kp);
            const ulonglong2* w = (const ulonglong2*)(wpB + kp * 80);
            ulonglong2 w0 = w[0], w1v = w[1], w2v = w[2], w3v = w[3], w4v = w[4];
            h0 = fma2(av.y, w0.y,  fma2(av.x, w0.x,  h0));
            h1 = fma2(av.y, w1v.y, fma2(av.x, w1v.x, h1));
            h2 = fma2(av.y, w2v.y, fma2(av.x, w2v.x, h2));
            h3 = fma2(av.y, w3v.y, fma2(av.x, w3v.x, h3));
            h4 = fma2(av.y, w4v.y, fma2(av.x, w4v.x, h4));
        }
        if (kh == 1) {
            ulonglong2* d = (ulonglong2*)pB;
            d[0] = make_ulonglong2(h0, h1);
            d[1] = make_ulonglong2(h2, h3);
            pB[4] = h4;
            if (tlow < 16) {  // out reduce on otherwise-idle threads
                const ulonglong2* pp = (const ulonglong2*)(sOutP + tlow * 8);
                ulonglong2 p0 = pp[0], p1 = pp[1], p2 = pp[2], p3 = pp[3];
                u64 s = add2(add2(add2(p0.x, p0.y), add2(p1.x, p1.y)),
                             add2(add2(p2.x, p2.y), add2(p3.x, p3.y)));
                s = add2(s, bo);
                float2 sf = *(float2*)&s;
                outp[(size_t)r0 * Tn + t] = sf.x;
                outp[(size_t)r1 * Tn + t] = sf.y;
            }
        }
        __syncthreads();  // b4: B partials ready

        if (kh == 0) {  // B-finish: combine halves, write next combined
            const ulonglong2* q = (const ulonglong2*)pB;
            ulonglong2 q0 = q[0], q1 = q[1];
            u64 q4 = pB[4];
            u64* dst = sComb + (cur ^ 1) * 672 + s2 * 42 + 5 * jg2;
            dst[0] = add2(h0, q0.x);
            dst[1] = add2(h1, q0.y);
            dst[2] = add2(h2, q1.x);
            dst[3] = add2(h3, q1.y);
            dst[4] = add2(h4, q4);
            if (tlow < 16)
                sComb[(cur ^ 1) * 672 + tlow * 42 + 40] = uN;
        }
        cur ^= 1;
    }
}

extern "C" void kernel_launch(void* const* d_in, const int* in_sizes, int n_in,
                              void* d_out, int out_size) {
    const float* inputs = (const float*)d_in[0];
    const float* w1  = (const float*)d_in[1];
    const float* b1  = (const float*)d_in[2];
    const float* w2  = (const float*)d_in[3];
    const float* b2  = (const float*)d_in[4];
    const float* ow1 = (const float*)d_in[5];
    const float* ob1 = (const float*)d_in[6];
    const float* ow2 = (const float*)d_in[7];
    const float* ob2 = (const float*)d_in[8];
    float* out = (float*)d_out;

    cudaFuncSetAttribute(rnn_kernel, cudaFuncAttributeMaxDynamicSharedMemorySize,
                         SMEM_BYTES);
    rnn_kernel<<<NBLK, NTHR, SMEM_BYTES>>>(inputs, w1, b1, w2, b2,
                                           ow1, ob1, ow2, ob2, out);
}

// round 5
// speedup vs baseline: 1.4158x; 1.4158x over previous
#include <cuda_runtime.h>

// RNN_64501818851829 — persistent fp32x2 RNN, GB300 sm_103a. Round 5.
// Base = Round-3 structure (128 blocks x 128 threads, 16 row-pairs/block,
// 2 barriers/step). Change: weights stored NON-duplicated as float4 (4 k's
// per neuron) -> weight LDS instruction count halves (the kernel is
// smem-crossbar-instruction bound); duplication to f32x2 happens in registers.

typedef unsigned long long u64;

static constexpr int Tn = 1024;
static constexpr int NTHR = 128;
static constexpr int NBLK = 128;           // 32 rows per block

__device__ __forceinline__ u64 fma2(u64 a, u64 b, u64 c) {
    u64 d; asm("fma.rn.f32x2 %0, %1, %2, %3;" : "=l"(d) : "l"(a), "l"(b), "l"(c));
    return d;
}
__device__ __forceinline__ u64 add2(u64 a, u64 b) {
    u64 d; asm("add.rn.f32x2 %0, %1, %2;" : "=l"(d) : "l"(a), "l"(b));
    return d;
}
__device__ __forceinline__ u64 mul2(u64 a, u64 b) {
    u64 d; asm("mul.rn.f32x2 %0, %1, %2;" : "=l"(d) : "l"(a), "l"(b));
    return d;
}
__device__ __forceinline__ u64 pack2(float lo, float hi) {
    u64 d; asm("mov.b64 %0, {%1, %2};" : "=l"(d) : "f"(lo), "f"(hi));
    return d;
}
__device__ __forceinline__ u64 dupf(float x) {
    u64 d; asm("mov.b64 %0, {%1, %1};" : "=l"(d) : "f"(x));
    return d;
}
// exact leaky-relu(0.01): max(x, 0.01*x)
__device__ __forceinline__ u64 lrelu2(u64 x, u64 c001) {
    u64 m = mul2(x, c001);
    float2 xf = *(float2*)&x, mf = *(float2*)&m, r;
    r.x = fmaxf(xf.x, mf.x);
    r.y = fmaxf(xf.y, mf.y);
    return *(u64*)&r;
}

__global__ void __launch_bounds__(NTHR, 1) rnn_kernel(
    const float* __restrict__ inputs,
    const float* __restrict__ w1,  const float* __restrict__ b1,
    const float* __restrict__ w2,  const float* __restrict__ b2,
    const float* __restrict__ ow1, const float* __restrict__ ob1,
    const float* __restrict__ ow2, const float* __restrict__ ob2,
    float* __restrict__ outp)
{
    // L1 weights (80 neurons x 40 hidden-k) non-dup: [kq][j] float4 (4 k's)
    __shared__ __align__(16) float fWA[10 * 80 * 4];   // 12800 B
    // L2 weights (40 x 40) non-dup: [kq][j] float4
    __shared__ __align__(16) float fWB[10 * 40 * 4];   //  6400 B
    __shared__ __align__(16) u64 sWu[96];              // u-column weights, dup
    __shared__ __align__(16) u64 sComb[2 * 16 * 42];   // [buf][pair][42]; [40]=u
    __shared__ __align__(16) u64 sA[16 * 42];          // h2h activations
    __shared__ __align__(16) u64 sOutP[16 * 8];        // h2o partial dots

    const int tid = threadIdx.x;
    const int baseRow = blockIdx.x * 32;

    // ---- weight staging ----
    // L1 hidden part: logical k 0..39 = combined col k+1 (combined = [h, u]).
    for (int idx = tid; idx < 40 * 80; idx += NTHR) {
        int kk = idx / 80, j = idx % 80;
        float w = (j < 40) ? w1[j * 41 + kk + 1] : ow1[(j - 40) * 41 + kk + 1];
        fWA[((kk >> 2) * 80 + j) * 4 + (kk & 3)] = w;
    }
    for (int j = tid; j < 80; j += NTHR) {   // u column (col 0), dup'd
        float w = (j < 40) ? w1[j * 41] : ow1[(j - 40) * 41];
        sWu[(j / 5) * 6 + (j % 5)] = dupf(w);
    }
    for (int idx = tid; idx < 40 * 40; idx += NTHR) {
        int kk = idx / 40, j = idx % 40;
        fWB[((kk >> 2) * 40 + j) * 4 + (kk & 3)] = w2[j * 40 + kk];
    }
    for (int idx = tid; idx < 2 * 16 * 42; idx += NTHR) sComb[idx] = 0ull;

    // ---- roles & constants ----
    const int s1  = tid & 7,  jg1 = tid >> 3;   // Phase A: 5 neurons, pairs s1,s1+8
    const int s2  = tid & 15, jg2 = tid >> 4;   // Phase B: 5 neurons, pair s2
    const bool isH2H = (jg1 < 8);
    const u64 c001 = dupf(0.01f);

    u64 bA[5], rW[5], bB[5];
#pragma unroll
    for (int i = 0; i < 5; i++) {
        int nA = (isH2H ? 5 * jg1 : 5 * (jg1 - 8)) + i;
        bA[i] = isH2H ? dupf(b1[nA]) : dupf(ob1[nA]);
        rW[i] = isH2H ? 0ull : dupf(ow2[5 * (jg1 - 8) + i]);
        bB[i] = dupf(b2[5 * jg2 + i]);
    }
    const u64 bo = dupf(ob2[0]);
    const int r0 = baseRow + 2 * (tid & 15);
    const int r1 = r0 + 1;

    __syncthreads();
    if (tid < 16)   // u at t=0 into buffer 0
        sComb[tid * 42 + 40] = pack2(inputs[(size_t)r0 * Tn], inputs[(size_t)r1 * Tn]);
    __syncthreads();

    const float4* wA4 = (const float4*)fWA + jg1 * 5;
    const float4* wB4 = (const float4*)fWB + jg2 * 5;
    const u64* wuA = sWu + jg1 * 6;

    int cur = 0;
    for (int t = 0; t < Tn; t++) {
        const u64* cbA = sComb + cur * 672 + s1 * 42;
        const u64* cbB = cbA + 8 * 42;

        // ---- Phase A: L1 (combined @ W1), 5 neurons x 2 pairs, k quads ----
        u64 aA0 = bA[0], aA1 = bA[1], aA2 = bA[2], aA3 = bA[3], aA4 = bA[4];
        u64 aB0 = bA[0], aB1 = bA[1], aB2 = bA[2], aB3 = bA[3], aB4 = bA[4];
#pragma unroll
        for (int kq = 0; kq < 10; kq++) {
            ulonglong2 ca01 = *(const ulonglong2*)(cbA + 4 * kq);
            ulonglong2 ca23 = *(const ulonglong2*)(cbA + 4 * kq + 2);
            ulonglong2 cb01 = *(const ulonglong2*)(cbB + 4 * kq);
            ulonglong2 cb23 = *(const ulonglong2*)(cbB + 4 * kq + 2);
            float4 v0 = wA4[kq * 80 + 0];
            float4 v1 = wA4[kq * 80 + 1];
            float4 v2 = wA4[kq * 80 + 2];
            float4 v3 = wA4[kq * 80 + 3];
            float4 v4 = wA4[kq * 80 + 4];
            u64 dx;
            dx = dupf(v0.x); aA0 = fma2(ca01.x, dx, aA0); aB0 = fma2(cb01.x, dx, aB0);
            dx = dupf(v0.y); aA0 = fma2(ca01.y, dx, aA0); aB0 = fma2(cb01.y, dx, aB0);
            dx = dupf(v0.z); aA0 = fma2(ca23.x, dx, aA0); aB0 = fma2(cb23.x, dx, aB0);
            dx = dupf(v0.w); aA0 = fma2(ca23.y, dx, aA0); aB0 = fma2(cb23.y, dx, aB0);
            dx = dupf(v1.x); aA1 = fma2(ca01.x, dx, aA1); aB1 = fma2(cb01.x, dx, aB1);
            dx = dupf(v1.y); aA1 = fma2(ca01.y, dx, aA1); aB1 = fma2(cb01.y, dx, aB1);
            dx = dupf(v1.z); aA1 = fma2(ca23.x, dx, aA1); aB1 = fma2(cb23.x, dx, aB1);
            dx = dupf(v1.w); aA1 = fma2(ca23.y, dx, aA1); aB1 = fma2(cb23.y, dx, aB1);
            dx = dupf(v2.x); aA2 = fma2(ca01.x, dx, aA2); aB2 = fma2(cb01.x, dx, aB2);
            dx = dupf(v2.y); aA2 = fma2(ca01.y, dx, aA2); aB2 = fma2(cb01.y, dx, aB2);
            dx = dupf(v2.z); aA2 = fma2(ca23.x, dx, aA2); aB2 = fma2(cb23.x, dx, aB2);
            dx = dupf(v2.w); aA2 = fma2(ca23.y, dx, aA2); aB2 = fma2(cb23.y, dx, aB2);
            dx = dupf(v3.x); aA3 = fma2(ca01.x, dx, aA3); aB3 = fma2(cb01.x, dx, aB3);
            dx = dupf(v3.y); aA3 = fma2(ca01.y, dx, aA3); aB3 = fma2(cb01.y, dx, aB3);
            dx = dupf(v3.z); aA3 = fma2(ca23.x, dx, aA3); aB3 = fma2(cb23.x, dx, aB3);
            dx = dupf(v3.w); aA3 = fma2(ca23.y, dx, aA3); aB3 = fma2(cb23.y, dx, aB3);
            dx = dupf(v4.x); aA4 = fma2(ca01.x, dx, aA4); aB4 = fma2(cb01.x, dx, aB4);
            dx = dupf(v4.y); aA4 = fma2(ca01.y, dx, aA4); aB4 = fma2(cb01.y, dx, aB4);
            dx = dupf(v4.z); aA4 = fma2(ca23.x, dx, aA4); aB4 = fma2(cb23.x, dx, aB4);
            dx = dupf(v4.w); aA4 = fma2(ca23.y, dx, aA4); aB4 = fma2(cb23.y, dx, aB4);
        }
        {   // u term (dup'd u64 weights, tiny)
            u64 ua = cbA[40], ub = cbB[40];
            ulonglong2 u01 = *(const ulonglong2*)(wuA);
            ulonglong2 u23 = *(const ulonglong2*)(wuA + 2);
            u64 u4 = wuA[4];
            aA0 = fma2(ua, u01.x, aA0); aB0 = fma2(ub, u01.x, aB0);
            aA1 = fma2(ua, u01.y, aA1); aB1 = fma2(ub, u01.y, aB1);
            aA2 = fma2(ua, u23.x, aA2); aB2 = fma2(ub, u23.x, aB2);
            aA3 = fma2(ua, u23.y, aA3); aB3 = fma2(ub, u23.y, aB3);
            aA4 = fma2(ua, u4,    aA4); aB4 = fma2(ub, u4,    aB4);
        }
        aA0 = lrelu2(aA0, c001); aB0 = lrelu2(aB0, c001);
        aA1 = lrelu2(aA1, c001); aB1 = lrelu2(aB1, c001);
        aA2 = lrelu2(aA2, c001); aB2 = lrelu2(aB2, c001);
        aA3 = lrelu2(aA3, c001); aB3 = lrelu2(aB3, c001);
        aA4 = lrelu2(aA4, c001); aB4 = lrelu2(aB4, c001);

        if (isH2H) {  // store h2h activations
            u64* dA = sA + s1 * 42 + 5 * jg1;
            u64* dB = sA + (s1 + 8) * 42 + 5 * jg1;
            dA[0] = aA0; dA[1] = aA1; dA[2] = aA2; dA[3] = aA3; dA[4] = aA4;
            dB[0] = aB0; dB[1] = aB1; dB[2] = aB2; dB[3] = aB3; dB[4] = aB4;
        } else {      // h2o partial output dots
            u64 pa = mul2(aA0, rW[0]);
            pa = fma2(aA1, rW[1], pa); pa = fma2(aA2, rW[2], pa);
            pa = fma2(aA3, rW[3], pa); pa = fma2(aA4, rW[4], pa);
            u64 pb = mul2(aB0, rW[0]);
            pb = fma2(aB1, rW[1], pb); pb = fma2(aB2, rW[2], pb);
            pb = fma2(aB3, rW[3], pb); pb = fma2(aB4, rW[4], pb);
            sOutP[s1 * 8 + (jg1 - 8)] = pa;
            sOutP[(s1 + 8) * 8 + (jg1 - 8)] = pb;
        }

        u64 uN = 0ull;
        if (tid < 16 && t + 1 < Tn)   // prefetch next step's input
            uN = pack2(inputs[(size_t)r0 * Tn + t + 1], inputs[(size_t)r1 * Tn + t + 1]);

        __syncthreads();  // acts + out partials ready

        // ---- Phase B: L2 hidden_new (acts @ W2), 5 neurons x 1 pair ----
        const u64* ap = sA + s2 * 42;
        u64 h0 = bB[0], h1 = bB[1], h2 = bB[2], h3 = bB[3], h4 = bB[4];
#pragma unroll
        for (int kq = 0; kq < 10; kq++) {
            ulonglong2 a01 = *(const ulonglong2*)(ap + 4 * kq);
            ulonglong2 a23 = *(const ulonglong2*)(ap + 4 * kq + 2);
            float4 v0 = wB4[kq * 40 + 0];
            float4 v1 = wB4[kq * 40 + 1];
            float4 v2 = wB4[kq * 40 + 2];
            float4 v3 = wB4[kq * 40 + 3];
            float4 v4 = wB4[kq * 40 + 4];
            u64 dx;
            dx = dupf(v0.x); h0 = fma2(a01.x, dx, h0);
            dx = dupf(v0.y); h0 = fma2(a01.y, dx, h0);
            dx = dupf(v0.z); h0 = fma2(a23.x, dx, h0);
            dx = dupf(v0.w); h0 = fma2(a23.y, dx, h0);
            dx = dupf(v1.x); h1 = fma2(a01.x, dx, h1);
            dx = dupf(v1.y); h1 = fma2(a01.y, dx, h1);
            dx = dupf(v1.z); h1 = fma2(a23.x, dx, h1);
            dx = dupf(v1.w); h1 = fma2(a23.y, dx, h1);
            dx = dupf(v2.x); h2 = fma2(a01.x, dx, h2);
            dx = dupf(v2.y); h2 = fma2(a01.y, dx, h2);
            dx = dupf(v2.z); h2 = fma2(a23.x, dx, h2);
            dx = dupf(v2.w); h2 = fma2(a23.y, dx, h2);
            dx = dupf(v3.x); h3 = fma2(a01.x, dx, h3);
            dx = dupf(v3.y); h3 = fma2(a01.y, dx, h3);
            dx = dupf(v3.z); h3 = fma2(a23.x, dx, h3);
            dx = dupf(v3.w); h3 = fma2(a23.y, dx, h3);
            dx = dupf(v4.x); h4 = fma2(a01.x, dx, h4);
            dx = dupf(v4.y); h4 = fma2(a01.y, dx, h4);
            dx = dupf(v4.z); h4 = fma2(a23.x, dx, h4);
            dx = dupf(v4.w); h4 = fma2(a23.y, dx, h4);
        }
        u64* dst = sComb + (cur ^ 1) * 672 + s2 * 42 + 5 * jg2;
        dst[0] = h0; dst[1] = h1; dst[2] = h2; dst[3] = h3; dst[4] = h4;

        if (tid < 16) {  // reduce h2o partials -> out[t], stash next u
            const ulonglong2* pp = (const ulonglong2*)(sOutP + tid * 8);
            ulonglong2 p0 = pp[0], p1 = pp[1], p2 = pp[2], p3 = pp[3];
            u64 s = add2(add2(add2(p0.x, p0.y), add2(p1.x, p1.y)),
                         add2(add2(p2.x, p2.y), add2(p3.x, p3.y)));
            s = add2(s, bo);
            float2 sf = *(float2*)&s;
            outp[(size_t)r0 * Tn + t] = sf.x;
            outp[(size_t)r1 * Tn + t] = sf.y;
            sComb[(cur ^ 1) * 672 + tid * 42 + 40] = uN;
        }
        __syncthreads();  // next combined ready
        cur ^= 1;
    }
}

extern "C" void kernel_launch(void* const* d_in, const int* in_sizes, int n_in,
                              void* d_out, int out_size) {
    const float* inputs = (const float*)d_in[0];
    const float* w1  = (const float*)d_in[1];
    const float* b1  = (const float*)d_in[2];
    const float* w2  = (const float*)d_in[3];
    const float* b2  = (const float*)d_in[4];
    const float* ow1 = (const float*)d_in[5];
    const float* ob1 = (const float*)d_in[6];
    const float* ow2 = (const float*)d_in[7];
    const float* ob2 = (const float*)d_in[8];
    float* out = (float*)d_out;

    rnn_kernel<<<NBLK, NTHR>>>(inputs, w1, b1, w2, b2,
                               ow1, ob1, ow2, ob2, out);
}

// round 6
// speedup vs baseline: 1.4164x; 1.0004x over previous
#include <cuda_runtime.h>

// RNN_64501818851829 — persistent fp32x2 RNN, GB300 sm_103a. Round 5.
// Base = Round-3 structure (128 blocks x 128 threads, 16 row-pairs/block,
// 2 barriers/step). Change: weights stored NON-duplicated as float4 (4 k's
// per neuron) -> weight LDS instruction count halves (the kernel is
// smem-crossbar-instruction bound); duplication to f32x2 happens in registers.

typedef unsigned long long u64;

static constexpr int Tn = 1024;
static constexpr int NTHR = 128;
static constexpr int NBLK = 128;           // 32 rows per block

__device__ __forceinline__ u64 fma2(u64 a, u64 b, u64 c) {
    u64 d; asm("fma.rn.f32x2 %0, %1, %2, %3;" : "=l"(d) : "l"(a), "l"(b), "l"(c));
    return d;
}
__device__ __forceinline__ u64 add2(u64 a, u64 b) {
    u64 d; asm("add.rn.f32x2 %0, %1, %2;" : "=l"(d) : "l"(a), "l"(b));
    return d;
}
__device__ __forceinline__ u64 mul2(u64 a, u64 b) {
    u64 d; asm("mul.rn.f32x2 %0, %1, %2;" : "=l"(d) : "l"(a), "l"(b));
    return d;
}
__device__ __forceinline__ u64 pack2(float lo, float hi) {
    u64 d; asm("mov.b64 %0, {%1, %2};" : "=l"(d) : "f"(lo), "f"(hi));
    return d;
}
__device__ __forceinline__ u64 dupf(float x) {
    u64 d; asm("mov.b64 %0, {%1, %1};" : "=l"(d) : "f"(x));
    return d;
}
// exact leaky-relu(0.01): max(x, 0.01*x)
__device__ __forceinline__ u64 lrelu2(u64 x, u64 c001) {
    u64 m = mul2(x, c001);
    float2 xf = *(float2*)&x, mf = *(float2*)&m, r;
    r.x = fmaxf(xf.x, mf.x);
    r.y = fmaxf(xf.y, mf.y);
    return *(u64*)&r;
}

__global__ void __launch_bounds__(NTHR, 1) rnn_kernel(
    const float* __restrict__ inputs,
    const float* __restrict__ w1,  const float* __restrict__ b1,
    const float* __restrict__ w2,  const float* __restrict__ b2,
    const float* __restrict__ ow1, const float* __restrict__ ob1,
    const float* __restrict__ ow2, const float* __restrict__ ob2,
    float* __restrict__ outp)
{
    // L1 weights (80 neurons x 40 hidden-k) non-dup: [kq][j] float4 (4 k's)
    __shared__ __align__(16) float fWA[10 * 80 * 4];   // 12800 B
    // L2 weights (40 x 40) non-dup: [kq][j] float4
    __shared__ __align__(16) float fWB[10 * 40 * 4];   //  6400 B
    __shared__ __align__(16) u64 sWu[96];              // u-column weights, dup
    __shared__ __align__(16) u64 sComb[2 * 16 * 42];   // [buf][pair][42]; [40]=u
    __shared__ __align__(16) u64 sA[16 * 42];          // h2h activations
    __shared__ __align__(16) u64 sOutP[16 * 8];        // h2o partial dots

    const int tid = threadIdx.x;
    const int baseRow = blockIdx.x * 32;

    // ---- weight staging ----
    // L1 hidden part: logical k 0..39 = combined col k+1 (combined = [h, u]).
    for (int idx = tid; idx < 40 * 80; idx += NTHR) {
        int kk = idx / 80, j = idx % 80;
        float w = (j < 40) ? w1[j * 41 + kk + 1] : ow1[(j - 40) * 41 + kk + 1];
        fWA[((kk >> 2) * 80 + j) * 4 + (kk & 3)] = w;
    }
    for (int j = tid; j < 80; j += NTHR) {   // u column (col 0), dup'd
        float w = (j < 40) ? w1[j * 41] : ow1[(j - 40) * 41];
        sWu[(j / 5) * 6 + (j % 5)] = dupf(w);
    }
    for (int idx = tid; idx < 40 * 40; idx += NTHR) {
        int kk = idx / 40, j = idx % 40;
        fWB[((kk >> 2) * 40 + j) * 4 + (kk & 3)] = w2[j * 40 + kk];
    }
    for (int idx = tid; idx < 2 * 16 * 42; idx += NTHR) sComb[idx] = 0ull;

    // ---- roles & constants ----
    const int s1  = tid & 7,  jg1 = tid >> 3;   // Phase A: 5 neurons, pairs s1,s1+8
    const int s2  = tid & 15, jg2 = tid >> 4;   // Phase B: 5 neurons, pair s2
    const bool isH2H = (jg1 < 8);
    const u64 c001 = dupf(0.01f);

    u64 bA[5], rW[5], bB[5];
#pragma unroll
    for (int i = 0; i < 5; i++) {
        int nA = (isH2H ? 5 * jg1 : 5 * (jg1 - 8)) + i;
        bA[i] = isH2H ? dupf(b1[nA]) : dupf(ob1[nA]);
        rW[i] = isH2H ? 0ull : dupf(ow2[5 * (jg1 - 8) + i]);
        bB[i] = dupf(b2[5 * jg2 + i]);
    }
    const u64 bo = dupf(ob2[0]);
    const int r0 = baseRow + 2 * (tid & 15);
    const int r1 = r0 + 1;

    __syncthreads();
    if (tid < 16)   // u at t=0 into buffer 0
        sComb[tid * 42 + 40] = pack2(inputs[(size_t)r0 * Tn], inputs[(size_t)r1 * Tn]);
    __syncthreads();

    const float4* wA4 = (const float4*)fWA + jg1 * 5;
    const float4* wB4 = (const float4*)fWB + jg2 * 5;
    const u64* wuA = sWu + jg1 * 6;

    int cur = 0;
    for (int t = 0; t < Tn; t++) {
        const u64* cbA = sComb + cur * 672 + s1 * 42;
        const u64* cbB = cbA + 8 * 42;

        // ---- Phase A: L1 (combined @ W1), 5 neurons x 2 pairs, k quads ----
        u64 aA0 = bA[0], aA1 = bA[1], aA2 = bA[2], aA3 = bA[3], aA4 = bA[4];
        u64 aB0 = bA[0], aB1 = bA[1], aB2 = bA[2], aB3 = bA[3], aB4 = bA[4];
#pragma unroll
        for (int kq = 0; kq < 10; kq++) {
            ulonglong2 ca01 = *(const ulonglong2*)(cbA + 4 * kq);
            ulonglong2 ca23 = *(const ulonglong2*)(cbA + 4 * kq + 2);
            ulonglong2 cb01 = *(const ulonglong2*)(cbB + 4 * kq);
            ulonglong2 cb23 = *(const ulonglong2*)(cbB + 4 * kq + 2);
            float4 v0 = wA4[kq * 80 + 0];
            float4 v1 = wA4[kq * 80 + 1];
            float4 v2 = wA4[kq * 80 + 2];
            float4 v3 = wA4[kq * 80 + 3];
            float4 v4 = wA4[kq * 80 + 4];
            u64 dx;
            dx = dupf(v0.x); aA0 = fma2(ca01.x, dx, aA0); aB0 = fma2(cb01.x, dx, aB0);
            dx = dupf(v0.y); aA0 = fma2(ca01.y, dx, aA0); aB0 = fma2(cb01.y, dx, aB0);
            dx = dupf(v0.z); aA0 = fma2(ca23.x, dx, aA0); aB0 = fma2(cb23.x, dx, aB0);
            dx = dupf(v0.w); aA0 = fma2(ca23.y, dx, aA0); aB0 = fma2(cb23.y, dx, aB0);
            dx = dupf(v1.x); aA1 = fma2(ca01.x, dx, aA1); aB1 = fma2(cb01.x, dx, aB1);
            dx = dupf(v1.y); aA1 = fma2(ca01.y, dx, aA1); aB1 = fma2(cb01.y, dx, aB1);
            dx = dupf(v1.z); aA1 = fma2(ca23.x, dx, aA1); aB1 = fma2(cb23.x, dx, aB1);
            dx = dupf(v1.w); aA1 = fma2(ca23.y, dx, aA1); aB1 = fma2(cb23.y, dx, aB1);
            dx = dupf(v2.x); aA2 = fma2(ca01.x, dx, aA2); aB2 = fma2(cb01.x, dx, aB2);
            dx = dupf(v2.y); aA2 = fma2(ca01.y, dx, aA2); aB2 = fma2(cb01.y, dx, aB2);
            dx = dupf(v2.z); aA2 = fma2(ca23.x, dx, aA2); aB2 = fma2(cb23.x, dx, aB2);
            dx = dupf(v2.w); aA2 = fma2(ca23.y, dx, aA2); aB2 = fma2(cb23.y, dx, aB2);
            dx = dupf(v3.x); aA3 = fma2(ca01.x, dx, aA3); aB3 = fma2(cb01.x, dx, aB3);
            dx = dupf(v3.y); aA3 = fma2(ca01.y, dx, aA3); aB3 = fma2(cb01.y, dx, aB3);
            dx = dupf(v3.z); aA3 = fma2(ca23.x, dx, aA3); aB3 = fma2(cb23.x, dx, aB3);
            dx = dupf(v3.w); aA3 = fma2(ca23.y, dx, aA3); aB3 = fma2(cb23.y, dx, aB3);
            dx = dupf(v4.x); aA4 = fma2(ca01.x, dx, aA4); aB4 = fma2(cb01.x, dx, aB4);
            dx = dupf(v4.y); aA4 = fma2(ca01.y, dx, aA4); aB4 = fma2(cb01.y, dx, aB4);
            dx = dupf(v4.z); aA4 = fma2(ca23.x, dx, aA4); aB4 = fma2(cb23.x, dx, aB4);
            dx = dupf(v4.w); aA4 = fma2(ca23.y, dx, aA4); aB4 = fma2(cb23.y, dx, aB4);
        }
        {   // u term (dup'd u64 weights, tiny)
            u64 ua = cbA[40], ub = cbB[40];
            ulonglong2 u01 = *(const ulonglong2*)(wuA);
            ulonglong2 u23 = *(const ulonglong2*)(wuA + 2);
            u64 u4 = wuA[4];
            aA0 = fma2(ua, u01.x, aA0); aB0 = fma2(ub, u01.x, aB0);
            aA1 = fma2(ua, u01.y, aA1); aB1 = fma2(ub, u01.y, aB1);
            aA2 = fma2(ua, u23.x, aA2); aB2 = fma2(ub, u23.x, aB2);
            aA3 = fma2(ua, u23.y, aA3); aB3 = fma2(ub, u23.y, aB3);
            aA4 = fma2(ua, u4,    aA4); aB4 = fma2(ub, u4,    aB4);
        }
        aA0 = lrelu2(aA0, c001); aB0 = lrelu2(aB0, c001);
        aA1 = lrelu2(aA1, c001); aB1 = lrelu2(aB1, c001);
        aA2 = lrelu2(aA2, c001); aB2 = lrelu2(aB2, c001);
        aA3 = lrelu2(aA3, c001); aB3 = lrelu2(aB3, c001);
        aA4 = lrelu2(aA4, c001); aB4 = lrelu2(aB4, c001);

        if (isH2H) {  // store h2h activations
            u64* dA = sA + s1 * 42 + 5 * jg1;
            u64* dB = sA + (s1 + 8) * 42 + 5 * jg1;
            dA[0] = aA0; dA[1] = aA1; dA[2] = aA2; dA[3] = aA3; dA[4] = aA4;
            dB[0] = aB0; dB[1] = aB1; dB[2] = aB2; dB[3] = aB3; dB[4] = aB4;
        } else {      // h2o partial output dots
            u64 pa = mul2(aA0, rW[0]);
            pa = fma2(aA1, rW[1], pa); pa = fma2(aA2, rW[2], pa);
            pa = fma2(aA3, rW[3], pa); pa = fma2(aA4, rW[4], pa);
            u64 pb = mul2(aB0, rW[0]);
            pb = fma2(aB1, rW[1], pb); pb = fma2(aB2, rW[2], pb);
            pb = fma2(aB3, rW[3], pb); pb = fma2(aB4, rW[4], pb);
            sOutP[s1 * 8 + (jg1 - 8)] = pa;
            sOutP[(s1 + 8) * 8 + (jg1 - 8)] = pb;
        }

        u64 uN = 0ull;
        if (tid < 16 && t + 1 < Tn)   // prefetch next step's input
            uN = pack2(inputs[(size_t)r0 * Tn + t + 1], inputs[(size_t)r1 * Tn + t + 1]);

        __syncthreads();  // acts + out partials ready

        // ---- Phase B: L2 hidden_new (acts @ W2), 5 neurons x 1 pair ----
        const u64* ap = sA + s2 * 42;
        u64 h0 = bB[0], h1 = bB[1], h2 = bB[2], h3 = bB[3], h4 = bB[4];
#pragma unroll
        for (int kq = 0; kq < 10; kq++) {
            ulonglong2 a01 = *(const ulonglong2*)(ap + 4 * kq);
            ulonglong2 a23 = *(const ulonglong2*)(ap + 4 * kq + 2);
            float4 v0 = wB4[kq * 40 + 0];
            float4 v1 = wB4[kq * 40 + 1];
            float4 v2 = wB4[kq * 40 + 2];
            float4 v3 = wB4[kq * 40 + 3];
            float4 v4 = wB4[kq * 40 + 4];
            u64 dx;
            dx = dupf(v0.x); h0 = fma2(a01.x, dx, h0);
            dx = dupf(v0.y); h0 = fma2(a01.y, dx, h0);
            dx = dupf(v0.z); h0 = fma2(a23.x, dx, h0);
            dx = dupf(v0.w); h0 = fma2(a23.y, dx, h0);
            dx = dupf(v1.x); h1 = fma2(a01.x, dx, h1);
            dx = dupf(v1.y); h1 = fma2(a01.y, dx, h1);
            dx = dupf(v1.z); h1 = fma2(a23.x, dx, h1);
            dx = dupf(v1.w); h1 = fma2(a23.y, dx, h1);
            dx = dupf(v2.x); h2 = fma2(a01.x, dx, h2);
            dx = dupf(v2.y); h2 = fma2(a01.y, dx, h2);
            dx = dupf(v2.z); h2 = fma2(a23.x, dx, h2);
            dx = dupf(v2.w); h2 = fma2(a23.y, dx, h2);
            dx = dupf(v3.x); h3 = fma2(a01.x, dx, h3);
            dx = dupf(v3.y); h3 = fma2(a01.y, dx, h3);
            dx = dupf(v3.z); h3 = fma2(a23.x, dx, h3);
            dx = dupf(v3.w); h3 = fma2(a23.y, dx, h3);
            dx = dupf(v4.x); h4 = fma2(a01.x, dx, h4);
            dx = dupf(v4.y); h4 = fma2(a01.y, dx, h4);
            dx = dupf(v4.z); h4 = fma2(a23.x, dx, h4);
            dx = dupf(v4.w); h4 = fma2(a23.y, dx, h4);
        }
        u64* dst = sComb + (cur ^ 1) * 672 + s2 * 42 + 5 * jg2;
        dst[0] = h0; dst[1] = h1; dst[2] = h2; dst[3] = h3; dst[4] = h4;

        if (tid < 16) {  // reduce h2o partials -> out[t], stash next u
            const ulonglong2* pp = (const ulonglong2*)(sOutP + tid * 8);
            ulonglong2 p0 = pp[0], p1 = pp[1], p2 = pp[2], p3 = pp[3];
            u64 s = add2(add2(add2(p0.x, p0.y), add2(p1.x, p1.y)),
                         add2(add2(p2.x, p2.y), add2(p3.x, p3.y)));
            s = add2(s, bo);
            float2 sf = *(float2*)&s;
            outp[(size_t)r0 * Tn + t] = sf.x;
            outp[(size_t)r1 * Tn + t] = sf.y;
            sComb[(cur ^ 1) * 672 + tid * 42 + 40] = uN;
        }
        __syncthreads();  // next combined ready
        cur ^= 1;
    }
}

extern "C" void kernel_launch(void* const* d_in, const int* in_sizes, int n_in,
                              void* d_out, int out_size) {
    const float* inputs = (const float*)d_in[0];
    const float* w1  = (const float*)d_in[1];
    const float* b1  = (const float*)d_in[2];
    const float* w2  = (const float*)d_in[3];
    const float* b2  = (const float*)d_in[4];
    const float* ow1 = (const float*)d_in[5];
    const float* ob1 = (const float*)d_in[6];
    const float* ow2 = (const float*)d_in[7];
    const float* ob2 = (const float*)d_in[8];
    float* out = (float*)d_out;

    rnn_kernel<<<NBLK, NTHR>>>(inputs, w1, b1, w2, b2,
                               ow1, ob1, ow2, ob2, out);
}

// round 7
// speedup vs baseline: 1.5265x; 1.0778x over previous
#include <cuda_runtime.h>

// RNN_64501818851829 — persistent fp32x2 RNN, GB300 sm_103a. Round 7.
// Warp-autonomous blocks: 512 blocks x 32 threads, 8 rows (4 f32x2 pairs)
// per block, entire T=1024 loop inside one warp -> __syncwarp only, and
// ~4 independent warps per SM hide each other's LDS latency.
// Tiling unchanged from R5 (ratio-optimal): Phase A thread = 5 neurons x
// 2 pairs, k in float4 quads (non-dup weights, dup in registers);
// Phase B thread = 5 neurons x 1 pair.

typedef unsigned long long u64;

static constexpr int Tn = 1024;
static constexpr int NTHR = 32;
static constexpr int NBLK = 512;           // 8 rows per block

__device__ __forceinline__ u64 fma2(u64 a, u64 b, u64 c) {
    u64 d; asm("fma.rn.f32x2 %0, %1, %2, %3;" : "=l"(d) : "l"(a), "l"(b), "l"(c));
    return d;
}
__device__ __forceinline__ u64 add2(u64 a, u64 b) {
    u64 d; asm("add.rn.f32x2 %0, %1, %2;" : "=l"(d) : "l"(a), "l"(b));
    return d;
}
__device__ __forceinline__ u64 mul2(u64 a, u64 b) {
    u64 d; asm("mul.rn.f32x2 %0, %1, %2;" : "=l"(d) : "l"(a), "l"(b));
    return d;
}
__device__ __forceinline__ u64 pack2(float lo, float hi) {
    u64 d; asm("mov.b64 %0, {%1, %2};" : "=l"(d) : "f"(lo), "f"(hi));
    return d;
}
__device__ __forceinline__ u64 dupf(float x) {
    u64 d; asm("mov.b64 %0, {%1, %1};" : "=l"(d) : "f"(x));
    return d;
}
// exact leaky-relu(0.01): max(x, 0.01*x)
__device__ __forceinline__ u64 lrelu2(u64 x, u64 c001) {
    u64 m = mul2(x, c001);
    float2 xf = *(float2*)&x, mf = *(float2*)&m, r;
    r.x = fmaxf(xf.x, mf.x);
    r.y = fmaxf(xf.y, mf.y);
    return *(u64*)&r;
}

__global__ void __launch_bounds__(NTHR) rnn_kernel(
    const float* __restrict__ inputs,
    const float* __restrict__ w1,  const float* __restrict__ b1,
    const float* __restrict__ w2,  const float* __restrict__ b2,
    const float* __restrict__ ow1, const float* __restrict__ ob1,
    const float* __restrict__ ow2, const float* __restrict__ ob2,
    float* __restrict__ outp)
{
    // L1 weights (80 neurons x 40 hidden-k) non-dup: [kq][j] float4 (4 k's)
    __shared__ __align__(16) float fWA[10 * 80 * 4];   // 12800 B
    // L2 weights (40 x 40) non-dup: [kq][j] float4
    __shared__ __align__(16) float fWB[10 * 40 * 4];   //  6400 B
    __shared__ __align__(16) u64 sWu[96];              // u-column weights, dup
    __shared__ __align__(16) u64 sComb[2 * 4 * 42];    // [buf][pair][42]; [40]=u
    __shared__ __align__(16) u64 sA[4 * 42];           // h2h activations
    __shared__ __align__(16) u64 sOutP[4 * 8];         // h2o partial dots

    const int tid = threadIdx.x;
    const int baseRow = blockIdx.x * 8;

    // ---- weight staging ----
    // L1 hidden part: logical k 0..39 = combined col k+1 (combined = [h, u]).
    for (int idx = tid; idx < 40 * 80; idx += NTHR) {
        int kk = idx / 80, j = idx % 80;
        float w = (j < 40) ? w1[j * 41 + kk + 1] : ow1[(j - 40) * 41 + kk + 1];
        fWA[((kk >> 2) * 80 + j) * 4 + (kk & 3)] = w;
    }
    for (int j = tid; j < 80; j += NTHR) {   // u column (col 0), dup'd
        float w = (j < 40) ? w1[j * 41] : ow1[(j - 40) * 41];
        sWu[(j / 5) * 6 + (j % 5)] = dupf(w);
    }
    for (int idx = tid; idx < 40 * 40; idx += NTHR) {
        int kk = idx / 40, j = idx % 40;
        fWB[((kk >> 2) * 40 + j) * 4 + (kk & 3)] = w2[j * 40 + kk];
    }
    for (int idx = tid; idx < 2 * 4 * 42; idx += NTHR) sComb[idx] = 0ull;

    // ---- roles & constants ----
    const int s1  = tid & 1, jg1 = tid >> 1;   // Phase A: 5 neurons, pairs s1,s1+2
    const int s2  = tid & 3, jg2 = tid >> 2;   // Phase B: 5 neurons, pair s2
    const bool isH2H = (jg1 < 8);
    const u64 c001 = dupf(0.01f);

    u64 bA[5], rW[5], bB[5];
#pragma unroll
    for (int i = 0; i < 5; i++) {
        int nA = (isH2H ? 5 * jg1 : 5 * (jg1 - 8)) + i;
        bA[i] = isH2H ? dupf(b1[nA]) : dupf(ob1[nA]);
        rW[i] = isH2H ? 0ull : dupf(ow2[5 * (jg1 - 8) + i]);
        bB[i] = dupf(b2[5 * jg2 + i]);
    }
    const u64 bo = dupf(ob2[0]);
    const int r0 = baseRow + 2 * (tid & 3);
    const int r1 = r0 + 1;

    __syncwarp();
    if (tid < 4)   // u at t=0 into buffer 0
        sComb[tid * 42 + 40] = pack2(inputs[(size_t)r0 * Tn], inputs[(size_t)r1 * Tn]);
    __syncwarp();

    const float4* wA4 = (const float4*)fWA + jg1 * 5;
    const float4* wB4 = (const float4*)fWB + jg2 * 5;
    const u64* wuA = sWu + jg1 * 6;

    int cur = 0;
    for (int t = 0; t < Tn; t++) {
        const u64* cbA = sComb + cur * 168 + s1 * 42;
        const u64* cbB = cbA + 2 * 42;

        // ---- Phase A: L1 (combined @ W1), 5 neurons x 2 pairs, k quads ----
        u64 aA0 = bA[0], aA1 = bA[1], aA2 = bA[2], aA3 = bA[3], aA4 = bA[4];
        u64 aB0 = bA[0], aB1 = bA[1], aB2 = bA[2], aB3 = bA[3], aB4 = bA[4];
#pragma unroll
        for (int kq = 0; kq < 10; kq++) {
            ulonglong2 ca01 = *(const ulonglong2*)(cbA + 4 * kq);
            ulonglong2 ca23 = *(const ulonglong2*)(cbA + 4 * kq + 2);
            ulonglong2 cb01 = *(const ulonglong2*)(cbB + 4 * kq);
            ulonglong2 cb23 = *(const ulonglong2*)(cbB + 4 * kq + 2);
            float4 v0 = wA4[kq * 80 + 0];
            float4 v1 = wA4[kq * 80 + 1];
            float4 v2 = wA4[kq * 80 + 2];
            float4 v3 = wA4[kq * 80 + 3];
            float4 v4 = wA4[kq * 80 + 4];
            u64 dx;
            dx = dupf(v0.x); aA0 = fma2(ca01.x, dx, aA0); aB0 = fma2(cb01.x, dx, aB0);
            dx = dupf(v0.y); aA0 = fma2(ca01.y, dx, aA0); aB0 = fma2(cb01.y, dx, aB0);
            dx = dupf(v0.z); aA0 = fma2(ca23.x, dx, aA0); aB0 = fma2(cb23.x, dx, aB0);
            dx = dupf(v0.w); aA0 = fma2(ca23.y, dx, aA0); aB0 = fma2(cb23.y, dx, aB0);
            dx = dupf(v1.x); aA1 = fma2(ca01.x, dx, aA1); aB1 = fma2(cb01.x, dx, aB1);
            dx = dupf(v1.y); aA1 = fma2(ca01.y, dx, aA1); aB1 = fma2(cb01.y, dx, aB1);
            dx = dupf(v1.z); aA1 = fma2(ca23.x, dx, aA1); aB1 = fma2(cb23.x, dx, aB1);
            dx = dupf(v1.w); aA1 = fma2(ca23.y, dx, aA1); aB1 = fma2(cb23.y, dx, aB1);
            dx = dupf(v2.x); aA2 = fma2(ca01.x, dx, aA2); aB2 = fma2(cb01.x, dx, aB2);
            dx = dupf(v2.y); aA2 = fma2(ca01.y, dx, aA2); aB2 = fma2(cb01.y, dx, aB2);
            dx = dupf(v2.z); aA2 = fma2(ca23.x, dx, aA2); aB2 = fma2(cb23.x, dx, aB2);
            dx = dupf(v2.w); aA2 = fma2(ca23.y, dx, aA2); aB2 = fma2(cb23.y, dx, aB2);
            dx = dupf(v3.x); aA3 = fma2(ca01.x, dx, aA3); aB3 = fma2(cb01.x, dx, aB3);
            dx = dupf(v3.y); aA3 = fma2(ca01.y, dx, aA3); aB3 = fma2(cb01.y, dx, aB3);
            dx = dupf(v3.z); aA3 = fma2(ca23.x, dx, aA3); aB3 = fma2(cb23.x, dx, aB3);
            dx = dupf(v3.w); aA3 = fma2(ca23.y, dx, aA3); aB3 = fma2(cb23.y, dx, aB3);
            dx = dupf(v4.x); aA4 = fma2(ca01.x, dx, aA4); aB4 = fma2(cb01.x, dx, aB4);
            dx = dupf(v4.y); aA4 = fma2(ca01.y, dx, aA4); aB4 = fma2(cb01.y, dx, aB4);
            dx = dupf(v4.z); aA4 = fma2(ca23.x, dx, aA4); aB4 = fma2(cb23.x, dx, aB4);
            dx = dupf(v4.w); aA4 = fma2(ca23.y, dx, aA4); aB4 = fma2(cb23.y, dx, aB4);
        }
        {   // u term (dup'd u64 weights, tiny)
            u64 ua = cbA[40], ub = cbB[40];
            ulonglong2 u01 = *(const ulonglong2*)(wuA);
            ulonglong2 u23 = *(const ulonglong2*)(wuA + 2);
            u64 u4 = wuA[4];
            aA0 = fma2(ua, u01.x, aA0); aB0 = fma2(ub, u01.x, aB0);
            aA1 = fma2(ua, u01.y, aA1); aB1 = fma2(ub, u01.y, aB1);
            aA2 = fma2(ua, u23.x, aA2); aB2 = fma2(ub, u23.x, aB2);
            aA3 = fma2(ua, u23.y, aA3); aB3 = fma2(ub, u23.y, aB3);
            aA4 = fma2(ua, u4,    aA4); aB4 = fma2(ub, u4,    aB4);
        }
        aA0 = lrelu2(aA0, c001); aB0 = lrelu2(aB0, c001);
        aA1 = lrelu2(aA1, c001); aB1 = lrelu2(aB1, c001);
        aA2 = lrelu2(aA2, c001); aB2 = lrelu2(aB2, c001);
        aA3 = lrelu2(aA3, c001); aB3 = lrelu2(aB3, c001);
        aA4 = lrelu2(aA4, c001); aB4 = lrelu2(aB4, c001);

        if (isH2H) {  // store h2h activations (pairs s1, s1+2)
            u64* dA = sA + s1 * 42 + 5 * jg1;
            u64* dB = sA + (s1 + 2) * 42 + 5 * jg1;
            dA[0] = aA0; dA[1] = aA1; dA[2] = aA2; dA[3] = aA3; dA[4] = aA4;
            dB[0] = aB0; dB[1] = aB1; dB[2] = aB2; dB[3] = aB3; dB[4] = aB4;
        } else {      // h2o partial output dots
            u64 pa = mul2(aA0, rW[0]);
            pa = fma2(aA1, rW[1], pa); pa = fma2(aA2, rW[2], pa);
            pa = fma2(aA3, rW[3], pa); pa = fma2(aA4, rW[4], pa);
            u64 pb = mul2(aB0, rW[0]);
            pb = fma2(aB1, rW[1], pb); pb = fma2(aB2, rW[2], pb);
            pb = fma2(aB3, rW[3], pb); pb = fma2(aB4, rW[4], pb);
            sOutP[s1 * 8 + (jg1 - 8)] = pa;
            sOutP[(s1 + 2) * 8 + (jg1 - 8)] = pb;
        }

        u64 uN = 0ull;
        if (tid < 4 && t + 1 < Tn)   // prefetch next step's input
            uN = pack2(inputs[(size_t)r0 * Tn + t + 1], inputs[(size_t)r1 * Tn + t + 1]);

        __syncwarp();  // acts + out partials ready

        // ---- Phase B: L2 hidden_new (acts @ W2), 5 neurons x 1 pair ----
        const u64* ap = sA + s2 * 42;
        u64 h0 = bB[0], h1 = bB[1], h2 = bB[2], h3 = bB[3], h4 = bB[4];
#pragma unroll
        for (int kq = 0; kq < 10; kq++) {
            ulonglong2 a01 = *(const ulonglong2*)(ap + 4 * kq);
            ulonglong2 a23 = *(const ulonglong2*)(ap + 4 * kq + 2);
            float4 v0 = wB4[kq * 40 + 0];
            float4 v1 = wB4[kq * 40 + 1];
            float4 v2 = wB4[kq * 40 + 2];
            float4 v3 = wB4[kq * 40 + 3];
            float4 v4 = wB4[kq * 40 + 4];
            u64 dx;
            dx = dupf(v0.x); h0 = fma2(a01.x, dx, h0);
            dx = dupf(v0.y); h0 = fma2(a01.y, dx, h0);
            dx = dupf(v0.z); h0 = fma2(a23.x, dx, h0);
            dx = dupf(v0.w); h0 = fma2(a23.y, dx, h0);
            dx = dupf(v1.x); h1 = fma2(a01.x, dx, h1);
            dx = dupf(v1.y); h1 = fma2(a01.y, dx, h1);
            dx = dupf(v1.z); h1 = fma2(a23.x, dx, h1);
            dx = dupf(v1.w); h1 = fma2(a23.y, dx, h1);
            dx = dupf(v2.x); h2 = fma2(a01.x, dx, h2);
            dx = dupf(v2.y); h2 = fma2(a01.y, dx, h2);
            dx = dupf(v2.z); h2 = fma2(a23.x, dx, h2);
            dx = dupf(v2.w); h2 = fma2(a23.y, dx, h2);
            dx = dupf(v3.x); h3 = fma2(a01.x, dx, h3);
            dx = dupf(v3.y); h3 = fma2(a01.y, dx, h3);
            dx = dupf(v3.z); h3 = fma2(a23.x, dx, h3);
            dx = dupf(v3.w); h3 = fma2(a23.y, dx, h3);
            dx = dupf(v4.x); h4 = fma2(a01.x, dx, h4);
            dx = dupf(v4.y); h4 = fma2(a01.y, dx, h4);
            dx = dupf(v4.z); h4 = fma2(a23.x, dx, h4);
            dx = dupf(v4.w); h4 = fma2(a23.y, dx, h4);
        }
        u64* dst = sComb + (cur ^ 1) * 168 + s2 * 42 + 5 * jg2;
        dst[0] = h0; dst[1] = h1; dst[2] = h2; dst[3] = h3; dst[4] = h4;

        if (tid < 4) {  // reduce h2o partials -> out[t], stash next u
            const ulonglong2* pp = (const ulonglong2*)(sOutP + tid * 8);
            ulonglong2 p0 = pp[0], p1 = pp[1], p2 = pp[2], p3 = pp[3];
            u64 s = add2(add2(add2(p0.x, p0.y), add2(p1.x, p1.y)),
                         add2(add2(p2.x, p2.y), add2(p3.x, p3.y)));
            s = add2(s, bo);
            float2 sf = *(float2*)&s;
            outp[(size_t)r0 * Tn + t] = sf.x;
            outp[(size_t)r1 * Tn + t] = sf.y;
            sComb[(cur ^ 1) * 168 + tid * 42 + 40] = uN;
        }
        __syncwarp();  // next combined ready
        cur ^= 1;
    }
}

extern "C" void kernel_launch(void* const* d_in, const int* in_sizes, int n_in,
                              void* d_out, int out_size) {
    const float* inputs = (const float*)d_in[0];
    const float* w1  = (const float*)d_in[1];
    const float* b1  = (const float*)d_in[2];
    const float* w2  = (const float*)d_in[3];
    const float* b2  = (const float*)d_in[4];
    const float* ow1 = (const float*)d_in[5];
    const float* ob1 = (const float*)d_in[6];
    const float* ow2 = (const float*)d_in[7];
    const float* ob2 = (const float*)d_in[8];
    float* out = (float*)d_out;

    rnn_kernel<<<NBLK, NTHR>>>(inputs, w1, b1, w2, b2,
                               ow1, ob1, ow2, ob2, out);
}

// round 8
// speedup vs baseline: 1.5849x; 1.0382x over previous
#include <cuda_runtime.h>

// RNN_64501818851829 — persistent fp32x2 RNN, GB300 sm_103a. Round 8.
// = Round 7 (512 warp-blocks x 32 thr, 8 rows/block, syncwarp-only) plus:
//   * __launch_bounds__(32,1): allow ptxas up to 255 regs
//   * manual register double-buffering of all inner-loop LDS (weights +
//     combined / activations) to hide the 29-cyc shared latency.

typedef unsigned long long u64;

static constexpr int Tn = 1024;
static constexpr int NTHR = 32;
static constexpr int NBLK = 512;           // 8 rows per block

__device__ __forceinline__ u64 fma2(u64 a, u64 b, u64 c) {
    u64 d; asm("fma.rn.f32x2 %0, %1, %2, %3;" : "=l"(d) : "l"(a), "l"(b), "l"(c));
    return d;
}
__device__ __forceinline__ u64 add2(u64 a, u64 b) {
    u64 d; asm("add.rn.f32x2 %0, %1, %2;" : "=l"(d) : "l"(a), "l"(b));
    return d;
}
__device__ __forceinline__ u64 mul2(u64 a, u64 b) {
    u64 d; asm("mul.rn.f32x2 %0, %1, %2;" : "=l"(d) : "l"(a), "l"(b));
    return d;
}
__device__ __forceinline__ u64 pack2(float lo, float hi) {
    u64 d; asm("mov.b64 %0, {%1, %2};" : "=l"(d) : "f"(lo), "f"(hi));
    return d;
}
__device__ __forceinline__ u64 dupf(float x) {
    u64 d; asm("mov.b64 %0, {%1, %1};" : "=l"(d) : "f"(x));
    return d;
}
// exact leaky-relu(0.01): max(x, 0.01*x)
__device__ __forceinline__ u64 lrelu2(u64 x, u64 c001) {
    u64 m = mul2(x, c001);
    float2 xf = *(float2*)&x, mf = *(float2*)&m, r;
    r.x = fmaxf(xf.x, mf.x);
    r.y = fmaxf(xf.y, mf.y);
    return *(u64*)&r;
}

__global__ void __launch_bounds__(NTHR, 1) rnn_kernel(
    const float* __restrict__ inputs,
    const float* __restrict__ w1,  const float* __restrict__ b1,
    const float* __restrict__ w2,  const float* __restrict__ b2,
    const float* __restrict__ ow1, const float* __restrict__ ob1,
    const float* __restrict__ ow2, const float* __restrict__ ob2,
    float* __restrict__ outp)
{
    // L1 weights (80 neurons x 40 hidden-k) non-dup: [kq][j] float4 (4 k's)
    __shared__ __align__(16) float fWA[10 * 80 * 4];   // 12800 B
    // L2 weights (40 x 40) non-dup: [kq][j] float4
    __shared__ __align__(16) float fWB[10 * 40 * 4];   //  6400 B
    __shared__ __align__(16) u64 sWu[96];              // u-column weights, dup
    __shared__ __align__(16) u64 sComb[2 * 4 * 42];    // [buf][pair][42]; [40]=u
    __shared__ __align__(16) u64 sA[4 * 42];           // h2h activations
    __shared__ __align__(16) u64 sOutP[4 * 8];         // h2o partial dots

    const int tid = threadIdx.x;
    const int baseRow = blockIdx.x * 8;

    // ---- weight staging ----
    for (int idx = tid; idx < 40 * 80; idx += NTHR) {
        int kk = idx / 80, j = idx % 80;
        float w = (j < 40) ? w1[j * 41 + kk + 1] : ow1[(j - 40) * 41 + kk + 1];
        fWA[((kk >> 2) * 80 + j) * 4 + (kk & 3)] = w;
    }
    for (int j = tid; j < 80; j += NTHR) {   // u column (col 0), dup'd
        float w = (j < 40) ? w1[j * 41] : ow1[(j - 40) * 41];
        sWu[(j / 5) * 6 + (j % 5)] = dupf(w);
    }
    for (int idx = tid; idx < 40 * 40; idx += NTHR) {
        int kk = idx / 40, j = idx % 40;
        fWB[((kk >> 2) * 40 + j) * 4 + (kk & 3)] = w2[j * 40 + kk];
    }
    for (int idx = tid; idx < 2 * 4 * 42; idx += NTHR) sComb[idx] = 0ull;

    // ---- roles & constants ----
    const int s1  = tid & 1, jg1 = tid >> 1;   // Phase A: 5 neurons, pairs s1,s1+2
    const int s2  = tid & 3, jg2 = tid >> 2;   // Phase B: 5 neurons, pair s2
    const bool isH2H = (jg1 < 8);
    const u64 c001 = dupf(0.01f);

    u64 bA[5], rW[5], bB[5];
#pragma unroll
    for (int i = 0; i < 5; i++) {
        int nA = (isH2H ? 5 * jg1 : 5 * (jg1 - 8)) + i;
        bA[i] = isH2H ? dupf(b1[nA]) : dupf(ob1[nA]);
        rW[i] = isH2H ? 0ull : dupf(ow2[5 * (jg1 - 8) + i]);
        bB[i] = dupf(b2[5 * jg2 + i]);
    }
    const u64 bo = dupf(ob2[0]);
    const int r0 = baseRow + 2 * (tid & 3);
    const int r1 = r0 + 1;

    __syncwarp();
    if (tid < 4)   // u at t=0 into buffer 0
        sComb[tid * 42 + 40] = pack2(inputs[(size_t)r0 * Tn], inputs[(size_t)r1 * Tn]);
    __syncwarp();

    const float4* wA4 = (const float4*)fWA + jg1 * 5;
    const float4* wB4 = (const float4*)fWB + jg2 * 5;
    const u64* wuA = sWu + jg1 * 6;

    int cur = 0;
    for (int t = 0; t < Tn; t++) {
        const u64* cbA = sComb + cur * 168 + s1 * 42;
        const u64* cbB = cbA + 2 * 42;

        // ---- Phase A: 5 neurons x 2 pairs, software-pipelined over kq ----
        u64 aA0 = bA[0], aA1 = bA[1], aA2 = bA[2], aA3 = bA[3], aA4 = bA[4];
        u64 aB0 = bA[0], aB1 = bA[1], aB2 = bA[2], aB3 = bA[3], aB4 = bA[4];

        // preload kq = 0
        ulonglong2 ca01 = *(const ulonglong2*)(cbA);
        ulonglong2 ca23 = *(const ulonglong2*)(cbA + 2);
        ulonglong2 cb01 = *(const ulonglong2*)(cbB);
        ulonglong2 cb23 = *(const ulonglong2*)(cbB + 2);
        float4 v0 = wA4[0], v1 = wA4[1], v2 = wA4[2], v3 = wA4[3], v4 = wA4[4];

#pragma unroll
        for (int kq = 0; kq < 10; kq++) {
            // issue next iteration's loads first (hide LDS latency)
            ulonglong2 nca01, nca23, ncb01, ncb23;
            float4 n0, n1, n2, n3, n4;
            if (kq < 9) {
                nca01 = *(const ulonglong2*)(cbA + 4 * (kq + 1));
                nca23 = *(const ulonglong2*)(cbA + 4 * (kq + 1) + 2);
                ncb01 = *(const ulonglong2*)(cbB + 4 * (kq + 1));
                ncb23 = *(const ulonglong2*)(cbB + 4 * (kq + 1) + 2);
                n0 = wA4[(kq + 1) * 80 + 0];
                n1 = wA4[(kq + 1) * 80 + 1];
                n2 = wA4[(kq + 1) * 80 + 2];
                n3 = wA4[(kq + 1) * 80 + 3];
                n4 = wA4[(kq + 1) * 80 + 4];
            }
            u64 dx;
            dx = dupf(v0.x); aA0 = fma2(ca01.x, dx, aA0); aB0 = fma2(cb01.x, dx, aB0);
            dx = dupf(v0.y); aA0 = fma2(ca01.y, dx, aA0); aB0 = fma2(cb01.y, dx, aB0);
            dx = dupf(v0.z); aA0 = fma2(ca23.x, dx, aA0); aB0 = fma2(cb23.x, dx, aB0);
            dx = dupf(v0.w); aA0 = fma2(ca23.y, dx, aA0); aB0 = fma2(cb23.y, dx, aB0);
            dx = dupf(v1.x); aA1 = fma2(ca01.x, dx, aA1); aB1 = fma2(cb01.x, dx, aB1);
            dx = dupf(v1.y); aA1 = fma2(ca01.y, dx, aA1); aB1 = fma2(cb01.y, dx, aB1);
            dx = dupf(v1.z); aA1 = fma2(ca23.x, dx, aA1); aB1 = fma2(cb23.x, dx, aB1);
            dx = dupf(v1.w); aA1 = fma2(ca23.y, dx, aA1); aB1 = fma2(cb23.y, dx, aB1);
            dx = dupf(v2.x); aA2 = fma2(ca01.x, dx, aA2); aB2 = fma2(cb01.x, dx, aB2);
            dx = dupf(v2.y); aA2 = fma2(ca01.y, dx, aA2); aB2 = fma2(cb01.y, dx, aB2);
            dx = dupf(v2.z); aA2 = fma2(ca23.x, dx, aA2); aB2 = fma2(cb23.x, dx, aB2);
            dx = dupf(v2.w); aA2 = fma2(ca23.y, dx, aA2); aB2 = fma2(cb23.y, dx, aB2);
            dx = dupf(v3.x); aA3 = fma2(ca01.x, dx, aA3); aB3 = fma2(cb01.x, dx, aB3);
            dx = dupf(v3.y); aA3 = fma2(ca01.y, dx, aA3); aB3 = fma2(cb01.y, dx, aB3);
            dx = dupf(v3.z); aA3 = fma2(ca23.x, dx, aA3); aB3 = fma2(cb23.x, dx, aB3);
            dx = dupf(v3.w); aA3 = fma2(ca23.y, dx, aA3); aB3 = fma2(cb23.y, dx, aB3);
            dx = dupf(v4.x); aA4 = fma2(ca01.x, dx, aA4); aB4 = fma2(cb01.x, dx, aB4);
            dx = dupf(v4.y); aA4 = fma2(ca01.y, dx, aA4); aB4 = fma2(cb01.y, dx, aB4);
            dx = dupf(v4.z); aA4 = fma2(ca23.x, dx, aA4); aB4 = fma2(cb23.x, dx, aB4);
            dx = dupf(v4.w); aA4 = fma2(ca23.y, dx, aA4); aB4 = fma2(cb23.y, dx, aB4);
            if (kq < 9) {
                ca01 = nca01; ca23 = nca23; cb01 = ncb01; cb23 = ncb23;
                v0 = n0; v1 = n1; v2 = n2; v3 = n3; v4 = n4;
            }
        }
        {   // u term (dup'd u64 weights, tiny)
            u64 ua = cbA[40], ub = cbB[40];
            ulonglong2 u01 = *(const ulonglong2*)(wuA);
            ulonglong2 u23 = *(const ulonglong2*)(wuA + 2);
            u64 u4 = wuA[4];
            aA0 = fma2(ua, u01.x, aA0); aB0 = fma2(ub, u01.x, aB0);
            aA1 = fma2(ua, u01.y, aA1); aB1 = fma2(ub, u01.y, aB1);
            aA2 = fma2(ua, u23.x, aA2); aB2 = fma2(ub, u23.x, aB2);
            aA3 = fma2(ua, u23.y, aA3); aB3 = fma2(ub, u23.y, aB3);
            aA4 = fma2(ua, u4,    aA4); aB4 = fma2(ub, u4,    aB4);
        }
        aA0 = lrelu2(aA0, c001); aB0 = lrelu2(aB0, c001);
        aA1 = lrelu2(aA1, c001); aB1 = lrelu2(aB1, c001);
        aA2 = lrelu2(aA2, c001); aB2 = lrelu2(aB2, c001);
        aA3 = lrelu2(aA3, c001); aB3 = lrelu2(aB3, c001);
        aA4 = lrelu2(aA4, c001); aB4 = lrelu2(aB4, c001);

        if (isH2H) {  // store h2h activations (pairs s1, s1+2)
            u64* dA = sA + s1 * 42 + 5 * jg1;
            u64* dB = sA + (s1 + 2) * 42 + 5 * jg1;
            dA[0] = aA0; dA[1] = aA1; dA[2] = aA2; dA[3] = aA3; dA[4] = aA4;
            dB[0] = aB0; dB[1] = aB1; dB[2] = aB2; dB[3] = aB3; dB[4] = aB4;
        } else {      // h2o partial output dots
            u64 pa = mul2(aA0, rW[0]);
            pa = fma2(aA1, rW[1], pa); pa = fma2(aA2, rW[2], pa);
            pa = fma2(aA3, rW[3], pa); pa = fma2(aA4, rW[4], pa);
            u64 pb = mul2(aB0, rW[0]);
            pb = fma2(aB1, rW[1], pb); pb = fma2(aB2, rW[2], pb);
            pb = fma2(aB3, rW[3], pb); pb = fma2(aB4, rW[4], pb);
            sOutP[s1 * 8 + (jg1 - 8)] = pa;
            sOutP[(s1 + 2) * 8 + (jg1 - 8)] = pb;
        }

        u64 uN = 0ull;
        if (tid < 4 && t + 1 < Tn)   // prefetch next step's input
            uN = pack2(inputs[(size_t)r0 * Tn + t + 1], inputs[(size_t)r1 * Tn + t + 1]);

        __syncwarp();  // acts + out partials ready

        // ---- Phase B: 5 neurons x 1 pair, software-pipelined over kq ----
        const u64* ap = sA + s2 * 42;
        u64 h0 = bB[0], h1 = bB[1], h2 = bB[2], h3 = bB[3], h4 = bB[4];

        ulonglong2 a01 = *(const ulonglong2*)(ap);
        ulonglong2 a23 = *(const ulonglong2*)(ap + 2);
        float4 q0 = wB4[0], q1 = wB4[1], q2 = wB4[2], q3 = wB4[3], q4 = wB4[4];

#pragma unroll
        for (int kq = 0; kq < 10; kq++) {
            ulonglong2 na01, na23;
            float4 m0, m1, m2, m3, m4;
            if (kq < 9) {
                na01 = *(const ulonglong2*)(ap + 4 * (kq + 1));
                na23 = *(const ulonglong2*)(ap + 4 * (kq + 1) + 2);
                m0 = wB4[(kq + 1) * 40 + 0];
                m1 = wB4[(kq + 1) * 40 + 1];
                m2 = wB4[(kq + 1) * 40 + 2];
                m3 = wB4[(kq + 1) * 40 + 3];
                m4 = wB4[(kq + 1) * 40 + 4];
            }
            u64 dx;
            dx = dupf(q0.x); h0 = fma2(a01.x, dx, h0);
            dx = dupf(q0.y); h0 = fma2(a01.y, dx, h0);
            dx = dupf(q0.z); h0 = fma2(a23.x, dx, h0);
            dx = dupf(q0.w); h0 = fma2(a23.y, dx, h0);
            dx = dupf(q1.x); h1 = fma2(a01.x, dx, h1);
            dx = dupf(q1.y); h1 = fma2(a01.y, dx, h1);
            dx = dupf(q1.z); h1 = fma2(a23.x, dx, h1);
            dx = dupf(q1.w); h1 = fma2(a23.y, dx, h1);
            dx = dupf(q2.x); h2 = fma2(a01.x, dx, h2);
            dx = dupf(q2.y); h2 = fma2(a01.y, dx, h2);
            dx = dupf(q2.z); h2 = fma2(a23.x, dx, h2);
            dx = dupf(q2.w); h2 = fma2(a23.y, dx, h2);
            dx = dupf(q3.x); h3 = fma2(a01.x, dx, h3);
            dx = dupf(q3.y); h3 = fma2(a01.y, dx, h3);
            dx = dupf(q3.z); h3 = fma2(a23.x, dx, h3);
            dx = dupf(q3.w); h3 = fma2(a23.y, dx, h3);
            dx = dupf(q4.x); h4 = fma2(a01.x, dx, h4);
            dx = dupf(q4.y); h4 = fma2(a01.y, dx, h4);
            dx = dupf(q4.z); h4 = fma2(a23.x, dx, h4);
            dx = dupf(q4.w); h4 = fma2(a23.y, dx, h4);
            if (kq < 9) {
                a01 = na01; a23 = na23;
                q0 = m0; q1 = m1; q2 = m2; q3 = m3; q4 = m4;
            }
        }
        u64* dst = sComb + (cur ^ 1) * 168 + s2 * 42 + 5 * jg2;
        dst[0] = h0; dst[1] = h1; dst[2] = h2; dst[3] = h3; dst[4] = h4;

        if (tid < 4) {  // reduce h2o partials -> out[t], stash next u
            const ulonglong2* pp = (const ulonglong2*)(sOutP + tid * 8);
            ulonglong2 p0 = pp[0], p1 = pp[1], p2 = pp[2], p3 = pp[3];
            u64 s = add2(add2(add2(p0.x, p0.y), add2(p1.x, p1.y)),
                         add2(add2(p2.x, p2.y), add2(p3.x, p3.y)));
            s = add2(s, bo);
            float2 sf = *(float2*)&s;
            outp[(size_t)r0 * Tn + t] = sf.x;
            outp[(size_t)r1 * Tn + t] = sf.y;
            sComb[(cur ^ 1) * 168 + tid * 42 + 40] = uN;
        }
        __syncwarp();  // next combined ready
        cur ^= 1;
    }
}

extern "C" void kernel_launch(void* const* d_in, const int* in_sizes, int n_in,
                              void* d_out, int out_size) {
    const float* inputs = (const float*)d_in[0];
    const float* w1  = (const float*)d_in[1];
    const float* b1  = (const float*)d_in[2];
    const float* w2  = (const float*)d_in[3];
    const float* b2  = (const float*)d_in[4];
    const float* ow1 = (const float*)d_in[5];
    const float* ob1 = (const float*)d_in[6];
    const float* ow2 = (const float*)d_in[7];
    const float* ob2 = (const float*)d_in[8];
    float* out = (float*)d_out;

    rnn_kernel<<<NBLK, NTHR>>>(inputs, w1, b1, w2, b2,
                               ow1, ob1, ow2, ob2, out);
}

// round 9
// speedup vs baseline: 2.0832x; 1.3145x over previous
#include <cuda_runtime.h>

// RNN_64501818851829 — GB300 sm_103a. Round 9.
// Algebraic fusion: h(t) = W2·a(t-1)+b2 enters step t linearly, so
//   a(t) = lrelu(W1u·u(t) + M·a(t-1) + c),  M = W1h·W2,  c = W1h·b2 + b1
//   o(t) = lrelu(OW1u·u(t) + N·a(t-1) + d), N = OW1h·W2, d = OW1h·b2 + ob1
//   out(t) = ow2·o(t) + ob2;   t=0: plain biases (h=0).
// One fused 80x40 GEMV per step (Phase B eliminated), one __syncwarp/step,
// out-reduction pipelined one step behind. 512 warp-blocks x 32 thr, 8 rows.

typedef unsigned long long u64;

static constexpr int Tn = 1024;
static constexpr int NTHR = 32;
static constexpr int NBLK = 512;           // 8 rows per block

__device__ __forceinline__ u64 fma2(u64 a, u64 b, u64 c) {
    u64 d; asm("fma.rn.f32x2 %0, %1, %2, %3;" : "=l"(d) : "l"(a), "l"(b), "l"(c));
    return d;
}
__device__ __forceinline__ u64 add2(u64 a, u64 b) {
    u64 d; asm("add.rn.f32x2 %0, %1, %2;" : "=l"(d) : "l"(a), "l"(b));
    return d;
}
__device__ __forceinline__ u64 mul2(u64 a, u64 b) {
    u64 d; asm("mul.rn.f32x2 %0, %1, %2;" : "=l"(d) : "l"(a), "l"(b));
    return d;
}
__device__ __forceinline__ u64 pack2(float lo, float hi) {
    u64 d; asm("mov.b64 %0, {%1, %2};" : "=l"(d) : "f"(lo), "f"(hi));
    return d;
}
__device__ __forceinline__ u64 dupf(float x) {
    u64 d; asm("mov.b64 %0, {%1, %1};" : "=l"(d) : "f"(x));
    return d;
}
// exact leaky-relu(0.01): max(x, 0.01*x)
__device__ __forceinline__ u64 lrelu2(u64 x, u64 c001) {
    u64 m = mul2(x, c001);
    float2 xf = *(float2*)&x, mf = *(float2*)&m, r;
    r.x = fmaxf(xf.x, mf.x);
    r.y = fmaxf(xf.y, mf.y);
    return *(u64*)&r;
}

__global__ void __launch_bounds__(NTHR, 1) rnn_kernel(
    const float* __restrict__ inputs,
    const float* __restrict__ w1,  const float* __restrict__ b1,
    const float* __restrict__ w2,  const float* __restrict__ b2,
    const float* __restrict__ ow1, const float* __restrict__ ob1,
    const float* __restrict__ ow2, const float* __restrict__ ob2,
    float* __restrict__ outp)
{
    // fused weights [M; N] (80 j x 40 k) non-dup: [kq][j] float4 (4 k's)
    __shared__ __align__(16) float fWA[10 * 80 * 4];   // 12800 B
    __shared__ __align__(16) u64 sWu[96];              // u-column weights, dup
    __shared__ __align__(16) u64 sZ[2 * 4 * 42];       // [buf][pair][42]; [40]=u
    __shared__ __align__(16) u64 sOutP[2 * 4 * 8];     // [buf][pair][8]
    // prologue scratch
    __shared__ __align__(16) float rW1[80 * 40];       // [j][m] hidden part
    __shared__ __align__(16) float rW2[40 * 40];       // w2 [m][k]
    __shared__ float rb2[40];

    const int tid = threadIdx.x;
    const int baseRow = blockIdx.x * 8;

    // ---- stage raw weights ----
    for (int idx = tid; idx < 80 * 40; idx += NTHR) {
        int j = idx / 40, m = idx % 40;
        rW1[idx] = (j < 40) ? w1[j * 41 + 1 + m] : ow1[(j - 40) * 41 + 1 + m];
    }
    for (int idx = tid; idx < 1600; idx += NTHR) rW2[idx] = w2[idx];
    for (int idx = tid; idx < 40; idx += NTHR) rb2[idx] = b2[idx];
    for (int j = tid; j < 80; j += NTHR) {     // u column (col 0), dup'd
        float w = (j < 40) ? w1[j * 41] : ow1[(j - 40) * 41];
        sWu[(j / 5) * 6 + (j % 5)] = dupf(w);
    }
    __syncwarp();

    // ---- roles ----
    const int s1 = tid & 1, jg1 = tid >> 1;    // 5 neurons, pairs s1 & s1+2
    const bool isH2H = (jg1 < 8);
    const int j0 = 5 * jg1;                    // global j base (0..75)
    const u64 c001 = dupf(0.01f);

    // ---- prologue: compute fused M/N = rW1 @ rW2 into fWA ----
    for (int pass = 0; pass < 2; pass++) {
        const int k0 = 20 * s1 + 10 * pass;
        float acc[5][10];
#pragma unroll
        for (int i = 0; i < 5; i++)
#pragma unroll
            for (int q = 0; q < 10; q++) acc[i][q] = 0.0f;
        for (int m = 0; m < 40; m++) {
            float a0 = rW1[(j0 + 0) * 40 + m];
            float a1 = rW1[(j0 + 1) * 40 + m];
            float a2 = rW1[(j0 + 2) * 40 + m];
            float a3 = rW1[(j0 + 3) * 40 + m];
            float a4 = rW1[(j0 + 4) * 40 + m];
#pragma unroll
            for (int q = 0; q < 10; q++) {
                float wv = rW2[m * 40 + k0 + q];
                acc[0][q] += a0 * wv;
                acc[1][q] += a1 * wv;
                acc[2][q] += a2 * wv;
                acc[3][q] += a3 * wv;
                acc[4][q] += a4 * wv;
            }
        }
#pragma unroll
        for (int i = 0; i < 5; i++)
#pragma unroll
            for (int q = 0; q < 10; q++) {
                int k = k0 + q;
                fWA[((k >> 2) * 80 + (j0 + i)) * 4 + (k & 3)] = acc[i][q];
            }
    }

    // ---- fused biases c/d and out-dot weights ----
    u64 bA[5], rW[5];
    {
        float cd[5] = {0, 0, 0, 0, 0};
        for (int m = 0; m < 40; m++) {
            float bv = rb2[m];
#pragma unroll
            for (int i = 0; i < 5; i++) cd[i] += rW1[(j0 + i) * 40 + m] * bv;
        }
#pragma unroll
        for (int i = 0; i < 5; i++) {
            float base = isH2H ? b1[j0 + i] : ob1[j0 - 40 + i];
            bA[i] = dupf(cd[i] + base);
            rW[i] = isH2H ? 0ull : dupf(ow2[j0 - 40 + i]);
        }
    }
    const u64 bo = dupf(ob2[0]);
    const int r0 = baseRow + 2 * (tid & 3);
    const int r1 = r0 + 1;
    __syncwarp();   // fWA ready

    // ---- special step t = 0 (h = 0: plain biases, u-column only) ----
    {
        const int pa = baseRow + 2 * s1, pb_ = baseRow + 2 * (s1 + 2);
        u64 u0a = pack2(inputs[(size_t)pa * Tn], inputs[(size_t)(pa + 1) * Tn]);
        u64 u0b = pack2(inputs[(size_t)pb_ * Tn], inputs[(size_t)(pb_ + 1) * Tn]);
        const u64* wu = sWu + jg1 * 6;
        u64 zA[5], zB[5];
#pragma unroll
        for (int i = 0; i < 5; i++) {
            float pbv = isH2H ? b1[j0 + i] : ob1[j0 - 40 + i];
            u64 bia = dupf(pbv);
            zA[i] = lrelu2(fma2(u0a, wu[i], bia), c001);
            zB[i] = lrelu2(fma2(u0b, wu[i], bia), c001);
        }
        if (isH2H) {
            u64* dA = sZ + s1 * 42 + j0;
            u64* dB = sZ + (s1 + 2) * 42 + j0;
#pragma unroll
            for (int i = 0; i < 5; i++) { dA[i] = zA[i]; dB[i] = zB[i]; }
        } else {
            u64 p = mul2(zA[0], rW[0]);
            p = fma2(zA[1], rW[1], p); p = fma2(zA[2], rW[2], p);
            p = fma2(zA[3], rW[3], p); p = fma2(zA[4], rW[4], p);
            u64 q = mul2(zB[0], rW[0]);
            q = fma2(zB[1], rW[1], q); q = fma2(zB[2], rW[2], q);
            q = fma2(zB[3], rW[3], q); q = fma2(zB[4], rW[4], q);
            sOutP[s1 * 8 + (jg1 - 8)] = p;
            sOutP[(s1 + 2) * 8 + (jg1 - 8)] = q;
        }
        if (tid < 4)   // u(1) into buffer 0
            sZ[tid * 42 + 40] = pack2(inputs[(size_t)r0 * Tn + 1],
                                      inputs[(size_t)r1 * Tn + 1]);
    }
    __syncwarp();

    // ---- main loop t = 1 .. 1023 (one syncwarp per step) ----
    const float4* wA4 = (const float4*)fWA + jg1 * 5;
    const u64* wuA = sWu + jg1 * 6;
    int cur = 0;
    for (int t = 1; t < Tn; t++) {
        // reduce out(t-1) from previous step's partials
        if (tid < 4) {
            const ulonglong2* pp = (const ulonglong2*)(sOutP + cur * 32 + tid * 8);
            ulonglong2 p0 = pp[0], p1 = pp[1], p2 = pp[2], p3 = pp[3];
            u64 s = add2(add2(add2(p0.x, p0.y), add2(p1.x, p1.y)),
                         add2(add2(p2.x, p2.y), add2(p3.x, p3.y)));
            s = add2(s, bo);
            float2 sf = *(float2*)&s;
            outp[(size_t)r0 * Tn + (t - 1)] = sf.x;
            outp[(size_t)r1 * Tn + (t - 1)] = sf.y;
        }

        const u64* cbA = sZ + cur * 168 + s1 * 42;
        const u64* cbB = cbA + 2 * 42;

        // fused GEMV: 5 neurons x 2 pairs, software-pipelined over kq
        u64 aA0 = bA[0], aA1 = bA[1], aA2 = bA[2], aA3 = bA[3], aA4 = bA[4];
        u64 aB0 = bA[0], aB1 = bA[1], aB2 = bA[2], aB3 = bA[3], aB4 = bA[4];

        ulonglong2 ca01 = *(const ulonglong2*)(cbA);
        ulonglong2 ca23 = *(const ulonglong2*)(cbA + 2);
        ulonglong2 cb01 = *(const ulonglong2*)(cbB);
        ulonglong2 cb23 = *(const ulonglong2*)(cbB + 2);
        float4 v0 = wA4[0], v1 = wA4[1], v2 = wA4[2], v3 = wA4[3], v4 = wA4[4];

#pragma unroll
        for (int kq = 0; kq < 10; kq++) {
            ulonglong2 nca01, nca23, ncb01, ncb23;
            float4 n0, n1, n2, n3, n4;
            if (kq < 9) {
                nca01 = *(const ulonglong2*)(cbA + 4 * (kq + 1));
                nca23 = *(const ulonglong2*)(cbA + 4 * (kq + 1) + 2);
                ncb01 = *(const ulonglong2*)(cbB + 4 * (kq + 1));
                ncb23 = *(const ulonglong2*)(cbB + 4 * (kq + 1) + 2);
                n0 = wA4[(kq + 1) * 80 + 0];
                n1 = wA4[(kq + 1) * 80 + 1];
                n2 = wA4[(kq + 1) * 80 + 2];
                n3 = wA4[(kq + 1) * 80 + 3];
                n4 = wA4[(kq + 1) * 80 + 4];
            }
            u64 dx;
            dx = dupf(v0.x); aA0 = fma2(ca01.x, dx, aA0); aB0 = fma2(cb01.x, dx, aB0);
            dx = dupf(v0.y); aA0 = fma2(ca01.y, dx, aA0); aB0 = fma2(cb01.y, dx, aB0);
            dx = dupf(v0.z); aA0 = fma2(ca23.x, dx, aA0); aB0 = fma2(cb23.x, dx, aB0);
            dx = dupf(v0.w); aA0 = fma2(ca23.y, dx, aA0); aB0 = fma2(cb23.y, dx, aB0);
            dx = dupf(v1.x); aA1 = fma2(ca01.x, dx, aA1); aB1 = fma2(cb01.x, dx, aB1);
            dx = dupf(v1.y); aA1 = fma2(ca01.y, dx, aA1); aB1 = fma2(cb01.y, dx, aB1);
            dx = dupf(v1.z); aA1 = fma2(ca23.x, dx, aA1); aB1 = fma2(cb23.x, dx, aB1);
            dx = dupf(v1.w); aA1 = fma2(ca23.y, dx, aA1); aB1 = fma2(cb23.y, dx, aB1);
            dx = dupf(v2.x); aA2 = fma2(ca01.x, dx, aA2); aB2 = fma2(cb01.x, dx, aB2);
            dx = dupf(v2.y); aA2 = fma2(ca01.y, dx, aA2); aB2 = fma2(cb01.y, dx, aB2);
            dx = dupf(v2.z); aA2 = fma2(ca23.x, dx, aA2); aB2 = fma2(cb23.x, dx, aB2);
            dx = dupf(v2.w); aA2 = fma2(ca23.y, dx, aA2); aB2 = fma2(cb23.y, dx, aB2);
            dx = dupf(v3.x); aA3 = fma2(ca01.x, dx, aA3); aB3 = fma2(cb01.x, dx, aB3);
            dx = dupf(v3.y); aA3 = fma2(ca01.y, dx, aA3); aB3 = fma2(cb01.y, dx, aB3);
            dx = dupf(v3.z); aA3 = fma2(ca23.x, dx, aA3); aB3 = fma2(cb23.x, dx, aB3);
            dx = dupf(v3.w); aA3 = fma2(ca23.y, dx, aA3); aB3 = fma2(cb23.y, dx, aB3);
            dx = dupf(v4.x); aA4 = fma2(ca01.x, dx, aA4); aB4 = fma2(cb01.x, dx, aB4);
            dx = dupf(v4.y); aA4 = fma2(ca01.y, dx, aA4); aB4 = fma2(cb01.y, dx, aB4);
            dx = dupf(v4.z); aA4 = fma2(ca23.x, dx, aA4); aB4 = fma2(cb23.x, dx, aB4);
            dx = dupf(v4.w); aA4 = fma2(ca23.y, dx, aA4); aB4 = fma2(cb23.y, dx, aB4);
            if (kq < 9) {
                ca01 = nca01; ca23 = nca23; cb01 = ncb01; cb23 = ncb23;
                v0 = n0; v1 = n1; v2 = n2; v3 = n3; v4 = n4;
            }
        }
        {   // u-term
            u64 ua = cbA[40], ub = cbB[40];
            ulonglong2 u01 = *(const ulonglong2*)(wuA);
            ulonglong2 u23 = *(const ulonglong2*)(wuA + 2);
            u64 u4 = wuA[4];
            aA0 = fma2(ua, u01.x, aA0); aB0 = fma2(ub, u01.x, aB0);
            aA1 = fma2(ua, u01.y, aA1); aB1 = fma2(ub, u01.y, aB1);
            aA2 = fma2(ua, u23.x, aA2); aB2 = fma2(ub, u23.x, aB2);
            aA3 = fma2(ua, u23.y, aA3); aB3 = fma2(ub, u23.y, aB3);
            aA4 = fma2(ua, u4,    aA4); aB4 = fma2(ub, u4,    aB4);
        }
        aA0 = lrelu2(aA0, c001); aB0 = lrelu2(aB0, c001);
        aA1 = lrelu2(aA1, c001); aB1 = lrelu2(aB1, c001);
        aA2 = lrelu2(aA2, c001); aB2 = lrelu2(aB2, c001);
        aA3 = lrelu2(aA3, c001); aB3 = lrelu2(aB3, c001);
        aA4 = lrelu2(aA4, c001); aB4 = lrelu2(aB4, c001);

        const int nxt = cur ^ 1;
        if (isH2H) {  // a(t) -> next buffer
            u64* dA = sZ + nxt * 168 + s1 * 42 + j0;
            u64* dB = sZ + nxt * 168 + (s1 + 2) * 42 + j0;
            dA[0] = aA0; dA[1] = aA1; dA[2] = aA2; dA[3] = aA3; dA[4] = aA4;
            dB[0] = aB0; dB[1] = aB1; dB[2] = aB2; dB[3] = aB3; dB[4] = aB4;
        } else {      // o(t) -> out-dot partials (reduced next step)
            u64 pa = mul2(aA0, rW[0]);
            pa = fma2(aA1, rW[1], pa); pa = fma2(aA2, rW[2], pa);
            pa = fma2(aA3, rW[3], pa); pa = fma2(aA4, rW[4], pa);
            u64 pb = mul2(aB0, rW[0]);
            pb = fma2(aB1, rW[1], pb); pb = fma2(aB2, rW[2], pb);
            pb = fma2(aB3, rW[3], pb); pb = fma2(aB4, rW[4], pb);
            sOutP[nxt * 32 + s1 * 8 + (jg1 - 8)] = pa;
            sOutP[nxt * 32 + (s1 + 2) * 8 + (jg1 - 8)] = pb;
        }
        if (tid < 4) {  // u(t+1) into next buffer
            u64 uN = 0ull;
            if (t + 1 < Tn)
                uN = pack2(inputs[(size_t)r0 * Tn + t + 1],
                           inputs[(size_t)r1 * Tn + t + 1]);
            sZ[nxt * 168 + tid * 42 + 40] = uN;
        }
        __syncwarp();
        cur = nxt;
    }

    // final out(1023)
    if (tid < 4) {
        const ulonglong2* pp = (const ulonglong2*)(sOutP + cur * 32 + tid * 8);
        ulonglong2 p0 = pp[0], p1 = pp[1], p2 = pp[2], p3 = pp[3];
        u64 s = add2(add2(add2(p0.x, p0.y), add2(p1.x, p1.y)),
                     add2(add2(p2.x, p2.y), add2(p3.x, p3.y)));
        s = add2(s, bo);
        float2 sf = *(float2*)&s;
        outp[(size_t)r0 * Tn + (Tn - 1)] = sf.x;
        outp[(size_t)r1 * Tn + (Tn - 1)] = sf.y;
    }
}

extern "C" void kernel_launch(void* const* d_in, const int* in_sizes, int n_in,
                              void* d_out, int out_size) {
    const float* inputs = (const float*)d_in[0];
    const float* w1  = (const float*)d_in[1];
    const float* b1  = (const float*)d_in[2];
    const float* w2  = (const float*)d_in[3];
    const float* b2  = (const float*)d_in[4];
    const float* ow1 = (const float*)d_in[5];
    const float* ob1 = (const float*)d_in[6];
    const float* ow2 = (const float*)d_in[7];
    const float* ob2 = (const float*)d_in[8];
    float* out = (float*)d_out;

    rnn_kernel<<<NBLK, NTHR>>>(inputs, w1, b1, w2, b2,
                               ow1, ob1, ow2, ob2, out);
}

// round 10
// speedup vs baseline: 2.2296x; 1.0702x over previous
#include <cuda_runtime.h>

// RNN_64501818851829 — GB300 sm_103a. Round 10.
// Fused recurrence (see R9): one 80x40 GEMV/step,
//   a(t) = lrelu(W1u·u(t) + M·a(t-1) + c),  M = W1h·W2,  c = W1h·b2 + b1
//   o(t) = lrelu(OW1u·u(t) + N·a(t-1) + d), out(t) = ow2·o(t) + ob2.
// This round: 1024 warp-blocks x 32 threads, 4 rows (2 f32x2 pairs) per
// block -> ~6.7 independent warps/SM to hide LDS/LDG latency; per-thread
// tile = 5 neurons x 1 pair (same 0.35 LDS/fma2 ratio); input LDG issued
// at the top of each step; smem ~22KB (M computed from global w1 + smem w2).

typedef unsigned long long u64;

static constexpr int Tn = 1024;
static constexpr int NTHR = 32;
static constexpr int NBLK = 1024;          // 4 rows per block

__device__ __forceinline__ u64 fma2(u64 a, u64 b, u64 c) {
    u64 d; asm("fma.rn.f32x2 %0, %1, %2, %3;" : "=l"(d) : "l"(a), "l"(b), "l"(c));
    return d;
}
__device__ __forceinline__ u64 add2(u64 a, u64 b) {
    u64 d; asm("add.rn.f32x2 %0, %1, %2;" : "=l"(d) : "l"(a), "l"(b));
    return d;
}
__device__ __forceinline__ u64 mul2(u64 a, u64 b) {
    u64 d; asm("mul.rn.f32x2 %0, %1, %2;" : "=l"(d) : "l"(a), "l"(b));
    return d;
}
__device__ __forceinline__ u64 pack2(float lo, float hi) {
    u64 d; asm("mov.b64 %0, {%1, %2};" : "=l"(d) : "f"(lo), "f"(hi));
    return d;
}
__device__ __forceinline__ void unpack2(u64 v, float& lo, float& hi) {
    asm("mov.b64 {%0, %1}, %2;" : "=f"(lo), "=f"(hi) : "l"(v));
}
__device__ __forceinline__ u64 dupf(float x) {
    u64 d; asm("mov.b64 %0, {%1, %1};" : "=l"(d) : "f"(x));
    return d;
}
// exact leaky-relu(0.01): max(x, 0.01*x)
__device__ __forceinline__ u64 lrelu2(u64 x, u64 c001) {
    u64 m = mul2(x, c001);
    float2 xf = *(float2*)&x, mf = *(float2*)&m, r;
    r.x = fmaxf(xf.x, mf.x);
    r.y = fmaxf(xf.y, mf.y);
    return *(u64*)&r;
}

__global__ void __launch_bounds__(NTHR, 1) rnn_kernel(
    const float* __restrict__ inputs,
    const float* __restrict__ w1,  const float* __restrict__ b1,
    const float* __restrict__ w2,  const float* __restrict__ b2,
    const float* __restrict__ ow1, const float* __restrict__ ob1,
    const float* __restrict__ ow2, const float* __restrict__ ob2,
    float* __restrict__ outp)
{
    // fused weights [M; N] (80 j x 40 k) non-dup: [kq][j] float4 (4 k's)
    __shared__ __align__(16) float fWA[10 * 80 * 4];   // 12800 B
    __shared__ __align__(16) float sW2f[40 * 40];      //  6400 B (w2 [m][k])
    __shared__ __align__(16) u64 sWu[96];              // u-column weights, dup
    __shared__ __align__(16) u64 sZ[2 * 2 * 42];       // [buf][pair][42]; [40]=u
    __shared__ __align__(16) u64 sOutP[2 * 2 * 8];     // [buf][pair][8]

    const int tid = threadIdx.x;
    const int baseRow = blockIdx.x * 4;
    const int s1 = tid & 1, jg1 = tid >> 1;    // pair, neuron-group (5 neurons)
    const bool isH2H = (jg1 < 8);
    const int j0 = 5 * jg1;                    // global neuron base (0..75)
    const u64 c001 = dupf(0.01f);

    // ---- stage w2 + u-column weights ----
    for (int idx = tid; idx < 1600; idx += NTHR) sW2f[idx] = w2[idx];
    for (int j = tid; j < 80; j += NTHR) {
        float w = (j < 40) ? w1[j * 41] : ow1[(j - 40) * 41];
        sWu[(j / 5) * 6 + (j % 5)] = dupf(w);
    }
    __syncwarp();

    // global pointer to this thread's 5 rows of the L1 hidden block (stride 41)
    const float* wrow = isH2H ? (w1 + j0 * 41 + 1)
                              : (ow1 + (j0 - 40) * 41 + 1);

    // ---- prologue: fused M/N = W1h @ W2 -> fWA (s1==0 twin computes) ----
    if (s1 == 0) {
        for (int pass = 0; pass < 4; pass++) {
            const int k0 = 10 * pass;
            u64 acc2[5][5];
#pragma unroll
            for (int i = 0; i < 5; i++)
#pragma unroll
                for (int q = 0; q < 5; q++) acc2[i][q] = 0ull;
            for (int m = 0; m < 40; m++) {
                u64 a[5];
#pragma unroll
                for (int i = 0; i < 5; i++) a[i] = dupf(wrow[i * 41 + m]);
                const u64* wv2 = (const u64*)(sW2f + m * 40 + k0);
#pragma unroll
                for (int q = 0; q < 5; q++) {
                    u64 wv = wv2[q];
#pragma unroll
                    for (int i = 0; i < 5; i++)
                        acc2[i][q] = fma2(a[i], wv, acc2[i][q]);
                }
            }
#pragma unroll
            for (int i = 0; i < 5; i++)
#pragma unroll
                for (int q = 0; q < 5; q++) {
                    float lo, hi; unpack2(acc2[i][q], lo, hi);
                    int k = k0 + 2 * q;
                    fWA[((k >> 2) * 80 + (j0 + i)) * 4 + (k & 3)] = lo;
                    k++;
                    fWA[((k >> 2) * 80 + (j0 + i)) * 4 + (k & 3)] = hi;
                }
        }
    }

    // ---- fused biases c/d and out-dot weights ----
    u64 bA[5], rW[5];
    {
        float cd[5] = {0, 0, 0, 0, 0};
        for (int m = 0; m < 40; m++) {
            float bv = b2[m];
#pragma unroll
            for (int i = 0; i < 5; i++) cd[i] += wrow[i * 41 + m] * bv;
        }
#pragma unroll
        for (int i = 0; i < 5; i++) {
            float base = isH2H ? b1[j0 + i] : ob1[j0 - 40 + i];
            bA[i] = dupf(cd[i] + base);
            rW[i] = isH2H ? 0ull : dupf(ow2[j0 - 40 + i]);
        }
    }
    const u64 bo = dupf(ob2[0]);
    __syncwarp();   // fWA visible to s1==1 twins

    // ---- special step t = 0 (h = 0: plain biases, u-column only) ----
    {
        const int pr0 = baseRow + 2 * s1, pr1 = pr0 + 1;
        u64 u0 = pack2(inputs[(size_t)pr0 * Tn], inputs[(size_t)pr1 * Tn]);
        const u64* wu = sWu + jg1 * 6;
        u64 z[5];
#pragma unroll
        for (int i = 0; i < 5; i++) {
            float pbv = isH2H ? b1[j0 + i] : ob1[j0 - 40 + i];
            z[i] = lrelu2(fma2(u0, wu[i], dupf(pbv)), c001);
        }
        if (isH2H) {
            u64* d = sZ + s1 * 42 + j0;
#pragma unroll
            for (int i = 0; i < 5; i++) d[i] = z[i];
        } else {
            u64 p = mul2(z[0], rW[0]);
            p = fma2(z[1], rW[1], p); p = fma2(z[2], rW[2], p);
            p = fma2(z[3], rW[3], p); p = fma2(z[4], rW[4], p);
            sOutP[s1 * 8 + (jg1 - 8)] = p;
        }
        if (tid < 2)   // u(1) into buffer 0
            sZ[tid * 42 + 40] = pack2(inputs[(size_t)(baseRow + 2 * tid) * Tn + 1],
                                      inputs[(size_t)(baseRow + 2 * tid + 1) * Tn + 1]);
    }
    __syncwarp();

    // ---- main loop t = 1 .. 1023 ----
    const float4* wA4 = (const float4*)fWA + jg1 * 5;
    const u64* wuA = sWu + jg1 * 6;
    const int r0 = baseRow + 2 * tid;          // rows for tid<2 duties
    const int r1v = r0 + 1;
    int cur = 0;
    for (int t = 1; t < Tn; t++) {
        // issue next-input LDG at the very top (hidden under the GEMV)
        u64 uN = 0ull;
        if (tid < 2 && t + 1 < Tn)
            uN = pack2(inputs[(size_t)r0 * Tn + t + 1],
                       inputs[(size_t)r1v * Tn + t + 1]);

        // reduce out(t-1) from previous step's partials
        if (tid < 2) {
            const ulonglong2* pp = (const ulonglong2*)(sOutP + cur * 16 + tid * 8);
            ulonglong2 p0 = pp[0], p1 = pp[1], p2 = pp[2], p3 = pp[3];
            u64 s = add2(add2(add2(p0.x, p0.y), add2(p1.x, p1.y)),
                         add2(add2(p2.x, p2.y), add2(p3.x, p3.y)));
            s = add2(s, bo);
            float lo, hi; unpack2(s, lo, hi);
            outp[(size_t)r0 * Tn + (t - 1)] = lo;
            outp[(size_t)r1v * Tn + (t - 1)] = hi;
        }

        const u64* zb = sZ + cur * 84 + s1 * 42;

        // fused GEMV: 5 neurons x 1 pair, software-pipelined over kq
        u64 a0 = bA[0], a1 = bA[1], a2 = bA[2], a3 = bA[3], a4 = bA[4];
        ulonglong2 z01 = *(const ulonglong2*)(zb);
        ulonglong2 z23 = *(const ulonglong2*)(zb + 2);
        float4 v0 = wA4[0], v1 = wA4[1], v2 = wA4[2], v3 = wA4[3], v4 = wA4[4];

#pragma unroll
        for (int kq = 0; kq < 10; kq++) {
            ulonglong2 nz01, nz23;
            float4 n0, n1, n2, n3, n4;
            if (kq < 9) {
                nz01 = *(const ulonglong2*)(zb + 4 * (kq + 1));
                nz23 = *(const ulonglong2*)(zb + 4 * (kq + 1) + 2);
                n0 = wA4[(kq + 1) * 80 + 0];
                n1 = wA4[(kq + 1) * 80 + 1];
                n2 = wA4[(kq + 1) * 80 + 2];
                n3 = wA4[(kq + 1) * 80 + 3];
                n4 = wA4[(kq + 1) * 80 + 4];
            }
            u64 dx;
            dx = dupf(v0.x); a0 = fma2(z01.x, dx, a0);
            dx = dupf(v0.y); a0 = fma2(z01.y, dx, a0);
            dx = dupf(v0.z); a0 = fma2(z23.x, dx, a0);
            dx = dupf(v0.w); a0 = fma2(z23.y, dx, a0);
            dx = dupf(v1.x); a1 = fma2(z01.x, dx, a1);
            dx = dupf(v1.y); a1 = fma2(z01.y, dx, a1);
            dx = dupf(v1.z); a1 = fma2(z23.x, dx, a1);
            dx = dupf(v1.w); a1 = fma2(z23.y, dx, a1);
            dx = dupf(v2.x); a2 = fma2(z01.x, dx, a2);
            dx = dupf(v2.y); a2 = fma2(z01.y, dx, a2);
            dx = dupf(v2.z); a2 = fma2(z23.x, dx, a2);
            dx = dupf(v2.w); a2 = fma2(z23.y, dx, a2);
            dx = dupf(v3.x); a3 = fma2(z01.x, dx, a3);
            dx = dupf(v3.y); a3 = fma2(z01.y, dx, a3);
            dx = dupf(v3.z); a3 = fma2(z23.x, dx, a3);
            dx = dupf(v3.w); a3 = fma2(z23.y, dx, a3);
            dx = dupf(v4.x); a4 = fma2(z01.x, dx, a4);
            dx = dupf(v4.y); a4 = fma2(z01.y, dx, a4);
            dx = dupf(v4.z); a4 = fma2(z23.x, dx, a4);
            dx = dupf(v4.w); a4 = fma2(z23.y, dx, a4);
            if (kq < 9) {
                z01 = nz01; z23 = nz23;
                v0 = n0; v1 = n1; v2 = n2; v3 = n3; v4 = n4;
            }
        }
        {   // u-term
            u64 ua = zb[40];
            ulonglong2 u01 = *(const ulonglong2*)(wuA);
            ulonglong2 u23 = *(const ulonglong2*)(wuA + 2);
            u64 u4 = wuA[4];
            a0 = fma2(ua, u01.x, a0);
            a1 = fma2(ua, u01.y, a1);
            a2 = fma2(ua, u23.x, a2);
            a3 = fma2(ua, u23.y, a3);
            a4 = fma2(ua, u4,    a4);
        }
        a0 = lrelu2(a0, c001);
        a1 = lrelu2(a1, c001);
        a2 = lrelu2(a2, c001);
        a3 = lrelu2(a3, c001);
        a4 = lrelu2(a4, c001);

        const int nxt = cur ^ 1;
        if (isH2H) {  // a(t) -> next buffer
            u64* d = sZ + nxt * 84 + s1 * 42 + j0;
            d[0] = a0; d[1] = a1; d[2] = a2; d[3] = a3; d[4] = a4;
        } else {      // o(t) -> out-dot partials (reduced next step)
            u64 p = mul2(a0, rW[0]);
            p = fma2(a1, rW[1], p); p = fma2(a2, rW[2], p);
            p = fma2(a3, rW[3], p); p = fma2(a4, rW[4], p);
            sOutP[nxt * 16 + s1 * 8 + (jg1 - 8)] = p;
        }
        if (tid < 2)   // u(t+1) into next buffer
            sZ[nxt * 84 + tid * 42 + 40] = uN;
        __syncwarp();
        cur = nxt;
    }

    // final out(1023)
    if (tid < 2) {
        const ulonglong2* pp = (const ulonglong2*)(sOutP + cur * 16 + tid * 8);
        ulonglong2 p0 = pp[0], p1 = pp[1], p2 = pp[2], p3 = pp[3];
        u64 s = add2(add2(add2(p0.x, p0.y), add2(p1.x, p1.y)),
                     add2(add2(p2.x, p2.y), add2(p3.x, p3.y)));
        s = add2(s, bo);
        float lo, hi; unpack2(s, lo, hi);
        outp[(size_t)r0 * Tn + (Tn - 1)] = lo;
        outp[(size_t)r1v * Tn + (Tn - 1)] = hi;
    }
}

extern "C" void kernel_launch(void* const* d_in, const int* in_sizes, int n_in,
                              void* d_out, int out_size) {
    const float* inputs = (const float*)d_in[0];
    const float* w1  = (const float*)d_in[1];
    const float* b1  = (const float*)d_in[2];
    const float* w2  = (const float*)d_in[3];
    const float* b2  = (const float*)d_in[4];
    const float* ow1 = (const float*)d_in[5];
    const float* ob1 = (const float*)d_in[6];
    const float* ow2 = (const float*)d_in[7];
    const float* ob2 = (const float*)d_in[8];
    float* out = (float*)d_out;

    rnn_kernel<<<NBLK, NTHR>>>(inputs, w1, b1, w2, b2,
                               ow1, ob1, ow2, ob2, out);
}